// round 7
// baseline (speedup 1.0000x reference)
#include <cuda_runtime.h>
#include <cuda_bf16.h>
#include <stdint.h>
#include <math.h>

#define BB 8
#define TT 4096
#define CC 384
#define HH 6
#define FF 64
#define EE 131072
#define DFF 1536
#define BT (BB*TT)            // 32768
#define NSLOPE 0.2f
#define LNEPS 1e-5f

// ---------------- scratch (device globals; no allocation allowed) ------------
__device__ float g_xn [BT*CC];          // LN1 output (tf32-rounded)
__device__ float g_h  [BT*CC];          // GAT projection h (full fp32)
__device__ float g_x1 [BT*CC];          // x + gat_out
__device__ float g_h2 [BT*CC];          // LN2 output (tf32-rounded)
__device__ float g_ffn[(size_t)BT*DFF]; // MLP hidden (tf32-rounded)
__device__ float g_wg_t[CC*CC];         // tf32-rounded weights
__device__ float g_w1_t[CC*DFF];
__device__ float g_w2_t[DFF*CC];
__device__ float g_asrc[BT*HH];
__device__ float g_adst[BT*HH];
__device__ int   g_deg [TT];
__device__ int   g_off [TT+1];
__device__ int   g_cur [TT];
__device__ int   g_csr_src[EE+TT];

__device__ __forceinline__ uint32_t f2tf32(float f) {
    uint32_t r;
    asm("cvt.rna.tf32.f32 %0, %1;" : "=r"(r) : "f"(f));
    return r;
}
__device__ __forceinline__ float f2tf32f(float f) {
    return __uint_as_float(f2tf32(f));
}

// ---------------- weight tf32 pre-round (all three weights, one launch) ------
#define NW1 (CC*CC/4)
#define NW2 (CC*DFF/4)
#define NW3 (DFF*CC/4)
__global__ void k_cvt_all(const float* __restrict__ wg,
                          const float* __restrict__ w1,
                          const float* __restrict__ w2) {
    int i = blockIdx.x*blockDim.x + threadIdx.x;
    const float* in; float* out; int idx;
    if (i < NW1) {
        in = wg; idx = i;
        float* p; p = g_wg_t; out = p;
    } else if (i < NW1 + NW2) {
        in = w1; idx = i - NW1; out = g_w1_t;
    } else if (i < NW1 + NW2 + NW3) {
        in = w2; idx = i - NW1 - NW2; out = g_w2_t;
    } else return;
    float4 v = ((const float4*)in)[idx];
    v.x = f2tf32f(v.x); v.y = f2tf32f(v.y);
    v.z = f2tf32f(v.z); v.w = f2tf32f(v.w);
    ((float4*)out)[idx] = v;
}

// ---------------- CSR build (per launch; edge list shared across batch) ------
__global__ void k_zero_deg() {
    int i = blockIdx.x*blockDim.x + threadIdx.x;
    if (i < TT) g_deg[i] = 0;
}

__global__ void k_hist(const int* __restrict__ ei) {
    int e = blockIdx.x*blockDim.x + threadIdx.x;
    if (e < EE) atomicAdd(&g_deg[ei[EE + e]], 1);   // dst row
}

__global__ void k_scan() {   // single block, 1024 threads, 4 nodes each
    __shared__ int s[1024];
    int tid  = threadIdx.x;
    int base = tid*4;
    int v0 = g_deg[base+0] + 1;   // +1 self loop
    int v1 = g_deg[base+1] + 1;
    int v2 = g_deg[base+2] + 1;
    int v3 = g_deg[base+3] + 1;
    s[tid] = v0+v1+v2+v3;
    __syncthreads();
    for (int d = 1; d < 1024; d <<= 1) {
        int t = (tid >= d) ? s[tid-d] : 0;
        __syncthreads();
        s[tid] += t;
        __syncthreads();
    }
    int excl = (tid == 0) ? 0 : s[tid-1];
    int o0 = excl, o1 = o0+v0, o2 = o1+v1, o3 = o2+v2;
    g_off[base+0]=o0; g_off[base+1]=o1; g_off[base+2]=o2; g_off[base+3]=o3;
    g_cur[base+0]=o0; g_cur[base+1]=o1; g_cur[base+2]=o2; g_cur[base+3]=o3;
    if (tid == 1023) g_off[TT] = s[1023];
}

__global__ void k_fill(const int* __restrict__ ei) {
    int i = blockIdx.x*blockDim.x + threadIdx.x;
    if (i < EE) {
        int d = ei[EE + i];
        int p = atomicAdd(&g_cur[d], 1);
        g_csr_src[p] = ei[i];                       // src row
    } else if (i < EE + TT) {
        int t = i - EE;
        int p = atomicAdd(&g_cur[t], 1);
        g_csr_src[p] = t;                           // self loop
    }
}

// ---------------- layer norm: warp per row, 12 elems/lane --------------------
template<int ROUND>
__global__ void __launch_bounds__(256) k_ln(const float* __restrict__ x,
                                            const float* __restrict__ g,
                                            const float* __restrict__ b,
                                            float* __restrict__ out) {
    int row  = blockIdx.x*8 + (threadIdx.x >> 5);
    int lane = threadIdx.x & 31;
    const float* xr = x + (size_t)row*CC;
    float v[12];
    float sum = 0.f;
    #pragma unroll
    for (int i = 0; i < 12; i++) { v[i] = xr[lane + i*32]; sum += v[i]; }
    #pragma unroll
    for (int o = 16; o; o >>= 1) sum += __shfl_xor_sync(0xffffffffu, sum, o);
    float mu  = sum * (1.f/CC);
    float var = 0.f;
    #pragma unroll
    for (int i = 0; i < 12; i++) { float d = v[i]-mu; var += d*d; }
    #pragma unroll
    for (int o = 16; o; o >>= 1) var += __shfl_xor_sync(0xffffffffu, var, o);
    float rs = rsqrtf(var*(1.f/CC) + LNEPS);
    float* orow = out + (size_t)row*CC;
    #pragma unroll
    for (int i = 0; i < 12; i++) {
        int c = lane + i*32;
        float o = (v[i]-mu)*rs*g[c] + b[c];
        orow[c] = ROUND ? f2tf32f(o) : o;
    }
}

// ---------------- tf32 tensor-core GEMM -------------------------------------
// C[MxN] = A[MxK] @ B[KxN] (+bias,+relu,+res,+tf32-round-output)
// Operands PRE-ROUNDED to tf32 -> mainloop is LDS+HMMA only.
// Block tile 256x128x16, 256 threads (8 warps = 4m x 2n), warp tile 64x64.
// Halves per-output smem-crossbar traffic vs 64x32 warp tile.
#define SA 20     // As row stride (floats): 16 + 4 pad
#define SB 136    // Bs row stride (floats): 128 + 8 pad

template<int RELU, int BIAS, int RES, int CVTOUT>
__global__ void __launch_bounds__(256) k_gemm_tc(const float* __restrict__ A,
                                                 const float* __restrict__ Bm,
                                                 const float* __restrict__ bias,
                                                 const float* __restrict__ res,
                                                 float* __restrict__ Cm,
                                                 int M, int N, int K) {
    __shared__ float As[2][256*SA];
    __shared__ float Bs[2][16*SB];

    int tid  = threadIdx.x;
    int lane = tid & 31;
    int w    = tid >> 5;
    int g    = lane >> 2;   // group id (0..7)
    int tg   = lane & 3;    // thread in group (0..3)
    int wm   = w & 3;       // warp m index (0..3)
    int wn   = w >> 2;      // warp n index (0..1)
    int bm   = blockIdx.y * 256;
    int bn   = blockIdx.x * 128;

    float c[4][8][4];
    #pragma unroll
    for (int i = 0; i < 4; i++)
        #pragma unroll
        for (int j = 0; j < 8; j++)
            #pragma unroll
            for (int k = 0; k < 4; k++) c[i][j][k] = 0.f;

    auto loadTile = [&](int k0, int buf) {
        #pragma unroll
        for (int li = 0; li < 4; li++) {          // A: 256x16 = 1024 float4
            int idx = tid + 256*li;
            int row = idx >> 2, kc = (idx & 3) * 4;
            uint32_t s = (uint32_t)__cvta_generic_to_shared(&As[buf][row*SA + kc]);
            const float* gp = A + (size_t)(bm + row)*K + k0 + kc;
            asm volatile("cp.async.cg.shared.global [%0], [%1], 16;\n" :: "r"(s), "l"(gp));
        }
        #pragma unroll
        for (int li = 0; li < 2; li++) {          // B: 16x128 = 512 float4
            int idx = tid + 256*li;
            int kr = idx >> 5, nc = (idx & 31) * 4;
            uint32_t s = (uint32_t)__cvta_generic_to_shared(&Bs[buf][kr*SB + nc]);
            const float* gp = Bm + (size_t)(k0 + kr)*N + bn + nc;
            asm volatile("cp.async.cg.shared.global [%0], [%1], 16;\n" :: "r"(s), "l"(gp));
        }
        asm volatile("cp.async.commit_group;\n");
    };

    int nk = K / 16;
    loadTile(0, 0);

    for (int i = 0; i < nk; i++) {
        int cur = i & 1;
        asm volatile("cp.async.wait_group 0;\n" ::: "memory");
        __syncthreads();
        if (i + 1 < nk) loadTile((i + 1)*16, (i + 1) & 1);

        const float* Ab = &As[cur][0];
        const float* Bb = &Bs[cur][0];
        #pragma unroll
        for (int ks = 0; ks < 2; ks++) {
            uint32_t a[4][4], b[8][2];
            #pragma unroll
            for (int mi = 0; mi < 4; mi++) {
                int r0 = wm*64 + mi*16 + g;
                a[mi][0] = __float_as_uint(Ab[ r0    *SA + ks*8 + tg    ]);
                a[mi][1] = __float_as_uint(Ab[(r0+8) *SA + ks*8 + tg    ]);
                a[mi][2] = __float_as_uint(Ab[ r0    *SA + ks*8 + tg + 4]);
                a[mi][3] = __float_as_uint(Ab[(r0+8) *SA + ks*8 + tg + 4]);
            }
            #pragma unroll
            for (int ni = 0; ni < 8; ni++) {
                int cc = wn*64 + ni*8 + g;
                b[ni][0] = __float_as_uint(Bb[(ks*8 + tg    )*SB + cc]);
                b[ni][1] = __float_as_uint(Bb[(ks*8 + tg + 4)*SB + cc]);
            }
            #pragma unroll
            for (int mi = 0; mi < 4; mi++)
                #pragma unroll
                for (int ni = 0; ni < 8; ni++)
                    asm volatile(
                        "mma.sync.aligned.m16n8k8.row.col.f32.tf32.tf32.f32 "
                        "{%0,%1,%2,%3}, {%4,%5,%6,%7}, {%8,%9}, {%0,%1,%2,%3};"
                        : "+f"(c[mi][ni][0]), "+f"(c[mi][ni][1]),
                          "+f"(c[mi][ni][2]), "+f"(c[mi][ni][3])
                        : "r"(a[mi][0]), "r"(a[mi][1]), "r"(a[mi][2]), "r"(a[mi][3]),
                          "r"(b[ni][0]), "r"(b[ni][1]));
        }
    }

    // epilogue
    #pragma unroll
    for (int mi = 0; mi < 4; mi++) {
        #pragma unroll
        for (int ni = 0; ni < 8; ni++) {
            int row = bm + wm*64 + mi*16 + g;
            int col = bn + wn*64 + ni*8 + tg*2;
            float bx = 0.f, by = 0.f;
            if (BIAS) { float2 bv = *(const float2*)&bias[col]; bx = bv.x; by = bv.y; }
            float v0 = c[mi][ni][0] + bx;
            float v1 = c[mi][ni][1] + by;
            float v2 = c[mi][ni][2] + bx;
            float v3 = c[mi][ni][3] + by;
            if (RELU) {
                v0 = fmaxf(v0, 0.f); v1 = fmaxf(v1, 0.f);
                v2 = fmaxf(v2, 0.f); v3 = fmaxf(v3, 0.f);
            }
            if (RES) {
                float2 r0 = *(const float2*)&res[(size_t)row*N + col];
                float2 r1 = *(const float2*)&res[(size_t)(row+8)*N + col];
                v0 += r0.x; v1 += r0.y; v2 += r1.x; v3 += r1.y;
            }
            if (CVTOUT) {
                v0 = f2tf32f(v0); v1 = f2tf32f(v1);
                v2 = f2tf32f(v2); v3 = f2tf32f(v3);
            }
            *(float2*)&Cm[(size_t)row*N + col]     = make_float2(v0, v1);
            *(float2*)&Cm[(size_t)(row+8)*N + col] = make_float2(v2, v3);
        }
    }
}

// ---------------- attention scores: warp per token ---------------------------
__global__ void __launch_bounds__(256) k_att(const float* __restrict__ att_src,
                                             const float* __restrict__ att_dst) {
    int bt   = blockIdx.x*8 + (threadIdx.x >> 5);
    int lane = threadIdx.x & 31;
    const float* hr = g_h + (size_t)bt*CC;
    #pragma unroll
    for (int hh = 0; hh < HH; hh++) {
        float2 hv = *(const float2*)(hr + hh*FF + lane*2);
        float2 as = *(const float2*)(att_src + hh*FF + lane*2);
        float2 ad = *(const float2*)(att_dst + hh*FF + lane*2);
        float ps = hv.x*as.x + hv.y*as.y;
        float pd = hv.x*ad.x + hv.y*ad.y;
        #pragma unroll
        for (int o = 16; o; o >>= 1) {
            ps += __shfl_xor_sync(0xffffffffu, ps, o);
            pd += __shfl_xor_sync(0xffffffffu, pd, o);
        }
        if (lane == 0) {
            g_asrc[bt*HH + hh] = ps;
            g_adst[bt*HH + hh] = pd;
        }
    }
}

// ---------------- GAT aggregate: ONE warp per (b,t), all 6 heads -------------
// lane covers cols {lane*4 + j*128}; each float4 lies fully in head
// h_j = j*2 + (lane>=16)  ->  3 online-softmax states per lane, no shuffles.
__global__ void __launch_bounds__(256) k_gat(const float* __restrict__ x,
                                             const float* __restrict__ b_gat,
                                             float* __restrict__ x1) {
    int w    = blockIdx.x*8 + (threadIdx.x >> 5);   // bt index in [0,BT)
    int lane = threadIdx.x & 31;
    int t = w % TT;
    int b = w / TT;
    int half = lane >> 4;                           // 0 or 1
    int cb = lane*4;

    float adst[3];
    #pragma unroll
    for (int j = 0; j < 3; j++) adst[j] = g_adst[w*HH + j*2 + half];

    int beg = g_off[t], end = g_off[t+1];
    const float* hbase = g_h + (size_t)b*TT*CC;
    const float* asrcb = g_asrc + (size_t)b*TT*HH;

    float4 acc[3];
    #pragma unroll
    for (int j = 0; j < 3; j++) acc[j] = make_float4(0.f,0.f,0.f,0.f);
    float m[3] = {-1e30f,-1e30f,-1e30f};
    float d[3] = {0.f,0.f,0.f};

    for (int i = beg; i < end; i++) {
        int s = g_csr_src[i];
        const float* hrow = hbase + (size_t)s*CC;
        const float* arow = asrcb + s*HH;
        #pragma unroll
        for (int j = 0; j < 3; j++) {
            float a = arow[j*2 + half] + adst[j];
            a = (a >= 0.f) ? a : NSLOPE*a;
            float nm = fmaxf(m[j], a);
            float sc = __expf(m[j] - nm);
            float wv = __expf(a - nm);
            float4 hv = *(const float4*)(hrow + j*128 + cb);
            acc[j].x = acc[j].x*sc + wv*hv.x;
            acc[j].y = acc[j].y*sc + wv*hv.y;
            acc[j].z = acc[j].z*sc + wv*hv.z;
            acc[j].w = acc[j].w*sc + wv*hv.w;
            d[j] = d[j]*sc + wv;
            m[j] = nm;
        }
    }

    #pragma unroll
    for (int j = 0; j < 3; j++) {
        float inv = 1.f/d[j];
        int col = j*128 + cb;
        size_t o = (size_t)w*CC + col;
        float4 xv = *(const float4*)(x + o);
        float4 bg = *(const float4*)(b_gat + col);
        float4 r;
        r.x = xv.x + acc[j].x*inv + bg.x;
        r.y = xv.y + acc[j].y*inv + bg.y;
        r.z = xv.z + acc[j].z*inv + bg.z;
        r.w = xv.w + acc[j].w*inv + bg.w;
        *(float4*)(x1 + o) = r;
    }
}

// ---------------- launch ----------------------------------------------------
extern "C" void kernel_launch(void* const* d_in, const int* in_sizes, int n_in,
                              void* d_out, int out_size) {
    const float* x       = (const float*)d_in[0];
    const int*   ei      = (const int*)  d_in[1];
    const float* W_gat   = (const float*)d_in[2];
    const float* att_src = (const float*)d_in[3];
    const float* att_dst = (const float*)d_in[4];
    const float* b_gat   = (const float*)d_in[5];
    const float* ln1_g   = (const float*)d_in[6];
    const float* ln1_b   = (const float*)d_in[7];
    const float* ln2_g   = (const float*)d_in[8];
    const float* ln2_b   = (const float*)d_in[9];
    const float* W1      = (const float*)d_in[10];
    const float* b1      = (const float*)d_in[11];
    const float* W2      = (const float*)d_in[12];
    const float* b2      = (const float*)d_in[13];
    float* out = (float*)d_out;

    float* p_xn;  cudaGetSymbolAddress((void**)&p_xn,  g_xn);
    float* p_h;   cudaGetSymbolAddress((void**)&p_h,   g_h);
    float* p_x1;  cudaGetSymbolAddress((void**)&p_x1,  g_x1);
    float* p_h2;  cudaGetSymbolAddress((void**)&p_h2,  g_h2);
    float* p_ffn; cudaGetSymbolAddress((void**)&p_ffn, g_ffn);
    float* p_wg;  cudaGetSymbolAddress((void**)&p_wg,  g_wg_t);
    float* p_w1;  cudaGetSymbolAddress((void**)&p_w1,  g_w1_t);
    float* p_w2;  cudaGetSymbolAddress((void**)&p_w2,  g_w2_t);

    // weight tf32 pre-round (one launch)
    k_cvt_all<<<(NW1+NW2+NW3+255)/256, 256>>>(W_gat, W1, W2);

    // CSR build (shared across batch)
    k_zero_deg<<<(TT+255)/256, 256>>>();
    k_hist<<<(EE+255)/256, 256>>>(ei);
    k_scan<<<1, 1024>>>();
    k_fill<<<(EE+TT+255)/256, 256>>>(ei);

    // LN1 (tf32-rounded output, feeds GEMM1 A)
    k_ln<1><<<BT/8, 256>>>(x, ln1_g, ln1_b, p_xn);

    // GAT projection: h = xn @ W_gat   [32768 x 384 x 384]
    k_gemm_tc<0,0,0,0><<<dim3(CC/128, BT/256), 256>>>(p_xn, p_wg, nullptr, nullptr,
                                                      p_h, BT, CC, CC);

    // per-token attention scores
    k_att<<<BT/8, 256>>>(att_src, att_dst);

    // gather + online softmax + residual  -> x1  (one warp per (b,t))
    k_gat<<<BT/8, 256>>>(x, b_gat, p_x1);

    // LN2 (tf32-rounded output, feeds GEMM2 A)
    k_ln<1><<<BT/8, 256>>>(p_x1, ln2_g, ln2_b, p_h2);

    // MLP: relu(h2 @ W1 + b1) -> ffn (tf32-rounded, feeds GEMM3 A)
    k_gemm_tc<1,1,0,1><<<dim3(DFF/128, BT/256), 256>>>(p_h2, p_w1, b1, nullptr,
                                                       p_ffn, BT, DFF, CC);
    // out = ffn @ W2 + b2 + x1          [32768 x 384 x 1536]
    k_gemm_tc<0,1,1,0><<<dim3(CC/128, BT/256), 256>>>(p_ffn, p_w2, b2, p_x1,
                                                      out, BT, CC, DFF);
}

// round 8
// speedup vs baseline: 1.0573x; 1.0573x over previous
#include <cuda_runtime.h>
#include <cuda_bf16.h>
#include <stdint.h>
#include <math.h>

#define BB 8
#define TT 4096
#define CC 384
#define HH 6
#define FF 64
#define EE 131072
#define DFF 1536
#define BT (BB*TT)            // 32768
#define NSLOPE 0.2f
#define LNEPS 1e-5f

// ---------------- scratch (device globals; no allocation allowed) ------------
__device__ float g_xn [BT*CC];                // LN1 output (tf32-rounded)
__device__ __nv_bfloat16 g_hb[BT*CC];         // GAT projection h (bf16)
__device__ float g_x1 [BT*CC];                // x + gat_out
__device__ float g_h2 [BT*CC];                // LN2 output (tf32-rounded)
__device__ float g_ffn[(size_t)BT*DFF];       // MLP hidden (tf32-rounded)
__device__ float g_wg_t[CC*CC];               // tf32-rounded weights
__device__ float g_w1_t[CC*DFF];
__device__ float g_w2_t[DFF*CC];
__device__ float g_asrc[BT*HH];
__device__ float g_adst[BT*HH];
__device__ int   g_deg [TT];
__device__ int   g_off [TT+1];
__device__ int   g_cur [TT];
__device__ int   g_csr_src[EE+TT];

__device__ __forceinline__ uint32_t f2tf32(float f) {
    uint32_t r;
    asm("cvt.rna.tf32.f32 %0, %1;" : "=r"(r) : "f"(f));
    return r;
}
__device__ __forceinline__ float f2tf32f(float f) {
    return __uint_as_float(f2tf32(f));
}

// ---------------- weight tf32 pre-round (all three weights, one launch) ------
#define NW1 (CC*CC/4)
#define NW2 (CC*DFF/4)
#define NW3 (DFF*CC/4)
__global__ void k_cvt_all(const float* __restrict__ wg,
                          const float* __restrict__ w1,
                          const float* __restrict__ w2) {
    int i = blockIdx.x*blockDim.x + threadIdx.x;
    const float* in; float* out; int idx;
    if (i < NW1) {
        in = wg; idx = i; out = g_wg_t;
    } else if (i < NW1 + NW2) {
        in = w1; idx = i - NW1; out = g_w1_t;
    } else if (i < NW1 + NW2 + NW3) {
        in = w2; idx = i - NW1 - NW2; out = g_w2_t;
    } else return;
    float4 v = ((const float4*)in)[idx];
    v.x = f2tf32f(v.x); v.y = f2tf32f(v.y);
    v.z = f2tf32f(v.z); v.w = f2tf32f(v.w);
    ((float4*)out)[idx] = v;
}

// ---------------- CSR build (per launch; edge list shared across batch) ------
__global__ void k_zero_deg() {
    int i = blockIdx.x*blockDim.x + threadIdx.x;
    if (i < TT) g_deg[i] = 0;
}

__global__ void k_hist(const int* __restrict__ ei) {
    int e = blockIdx.x*blockDim.x + threadIdx.x;
    if (e < EE) atomicAdd(&g_deg[ei[EE + e]], 1);   // dst row
}

__global__ void k_scan() {   // single block, 1024 threads, 4 nodes each
    __shared__ int s[1024];
    int tid  = threadIdx.x;
    int base = tid*4;
    int v0 = g_deg[base+0] + 1;   // +1 self loop
    int v1 = g_deg[base+1] + 1;
    int v2 = g_deg[base+2] + 1;
    int v3 = g_deg[base+3] + 1;
    s[tid] = v0+v1+v2+v3;
    __syncthreads();
    for (int d = 1; d < 1024; d <<= 1) {
        int t = (tid >= d) ? s[tid-d] : 0;
        __syncthreads();
        s[tid] += t;
        __syncthreads();
    }
    int excl = (tid == 0) ? 0 : s[tid-1];
    int o0 = excl, o1 = o0+v0, o2 = o1+v1, o3 = o2+v2;
    g_off[base+0]=o0; g_off[base+1]=o1; g_off[base+2]=o2; g_off[base+3]=o3;
    g_cur[base+0]=o0; g_cur[base+1]=o1; g_cur[base+2]=o2; g_cur[base+3]=o3;
    if (tid == 1023) g_off[TT] = s[1023];
}

__global__ void k_fill(const int* __restrict__ ei) {
    int i = blockIdx.x*blockDim.x + threadIdx.x;
    if (i < EE) {
        int d = ei[EE + i];
        int p = atomicAdd(&g_cur[d], 1);
        g_csr_src[p] = ei[i];                       // src row
    } else if (i < EE + TT) {
        int t = i - EE;
        int p = atomicAdd(&g_cur[t], 1);
        g_csr_src[p] = t;                           // self loop
    }
}

// ---------------- layer norm: warp per row, 12 elems/lane --------------------
template<int ROUND>
__global__ void __launch_bounds__(256) k_ln(const float* __restrict__ x,
                                            const float* __restrict__ g,
                                            const float* __restrict__ b,
                                            float* __restrict__ out) {
    int row  = blockIdx.x*8 + (threadIdx.x >> 5);
    int lane = threadIdx.x & 31;
    const float* xr = x + (size_t)row*CC;
    float v[12];
    float sum = 0.f;
    #pragma unroll
    for (int i = 0; i < 12; i++) { v[i] = xr[lane + i*32]; sum += v[i]; }
    #pragma unroll
    for (int o = 16; o; o >>= 1) sum += __shfl_xor_sync(0xffffffffu, sum, o);
    float mu  = sum * (1.f/CC);
    float var = 0.f;
    #pragma unroll
    for (int i = 0; i < 12; i++) { float d = v[i]-mu; var += d*d; }
    #pragma unroll
    for (int o = 16; o; o >>= 1) var += __shfl_xor_sync(0xffffffffu, var, o);
    float rs = rsqrtf(var*(1.f/CC) + LNEPS);
    float* orow = out + (size_t)row*CC;
    #pragma unroll
    for (int i = 0; i < 12; i++) {
        int c = lane + i*32;
        float o = (v[i]-mu)*rs*g[c] + b[c];
        orow[c] = ROUND ? f2tf32f(o) : o;
    }
}

// ---------------- tf32 tensor-core GEMM (R6 config: 128x128x16, 2 CTA/SM) ----
// C[MxN] = A[MxK] @ B[KxN] (+bias,+relu,+res,+tf32-round-out | bf16-out)
// Operands PRE-ROUNDED to tf32 -> mainloop is LDS+HMMA only.
// 256 threads (8 warps, 2m x 4n), warp tile 64x32.
#define SA 20     // As row stride (floats): 16 + 4 pad
#define SB 136    // Bs row stride (floats): 128 + 8 pad

template<int RELU, int BIAS, int RES, int CVTOUT, int OUTBF16>
__global__ void __launch_bounds__(256) k_gemm_tc(const float* __restrict__ A,
                                                 const float* __restrict__ Bm,
                                                 const float* __restrict__ bias,
                                                 const float* __restrict__ res,
                                                 void* __restrict__ Cm,
                                                 int M, int N, int K) {
    __shared__ float As[2][128*SA];
    __shared__ float Bs[2][16*SB];

    int tid  = threadIdx.x;
    int lane = tid & 31;
    int w    = tid >> 5;
    int g    = lane >> 2;   // group id (0..7)
    int tg   = lane & 3;    // thread in group (0..3)
    int wm   = w & 1;       // warp m index (0..1)
    int wn   = w >> 1;      // warp n index (0..3)
    int bm   = blockIdx.y * 128;
    int bn   = blockIdx.x * 128;

    float c[4][4][4];
    #pragma unroll
    for (int i = 0; i < 4; i++)
        #pragma unroll
        for (int j = 0; j < 4; j++)
            #pragma unroll
            for (int k = 0; k < 4; k++) c[i][j][k] = 0.f;

    auto loadTile = [&](int k0, int buf) {
        #pragma unroll
        for (int li = 0; li < 2; li++) {          // A: 128x16 = 512 float4
            int idx = tid + 256*li;
            int row = idx >> 2, kc = (idx & 3) * 4;
            uint32_t s = (uint32_t)__cvta_generic_to_shared(&As[buf][row*SA + kc]);
            const float* gp = A + (size_t)(bm + row)*K + k0 + kc;
            asm volatile("cp.async.cg.shared.global [%0], [%1], 16;\n" :: "r"(s), "l"(gp));
        }
        #pragma unroll
        for (int li = 0; li < 2; li++) {          // B: 16x128 = 512 float4
            int idx = tid + 256*li;
            int kr = idx >> 5, nc = (idx & 31) * 4;
            uint32_t s = (uint32_t)__cvta_generic_to_shared(&Bs[buf][kr*SB + nc]);
            const float* gp = Bm + (size_t)(k0 + kr)*N + bn + nc;
            asm volatile("cp.async.cg.shared.global [%0], [%1], 16;\n" :: "r"(s), "l"(gp));
        }
        asm volatile("cp.async.commit_group;\n");
    };

    int nk = K / 16;
    loadTile(0, 0);

    for (int i = 0; i < nk; i++) {
        int cur = i & 1;
        asm volatile("cp.async.wait_group 0;\n" ::: "memory");
        __syncthreads();
        if (i + 1 < nk) loadTile((i + 1)*16, (i + 1) & 1);

        const float* Ab = &As[cur][0];
        const float* Bb = &Bs[cur][0];
        #pragma unroll
        for (int ks = 0; ks < 2; ks++) {
            uint32_t a[4][4], b[4][2];
            #pragma unroll
            for (int mi = 0; mi < 4; mi++) {
                int r0 = wm*64 + mi*16 + g;
                a[mi][0] = __float_as_uint(Ab[ r0    *SA + ks*8 + tg    ]);
                a[mi][1] = __float_as_uint(Ab[(r0+8) *SA + ks*8 + tg    ]);
                a[mi][2] = __float_as_uint(Ab[ r0    *SA + ks*8 + tg + 4]);
                a[mi][3] = __float_as_uint(Ab[(r0+8) *SA + ks*8 + tg + 4]);
            }
            #pragma unroll
            for (int ni = 0; ni < 4; ni++) {
                int cc = wn*32 + ni*8 + g;
                b[ni][0] = __float_as_uint(Bb[(ks*8 + tg    )*SB + cc]);
                b[ni][1] = __float_as_uint(Bb[(ks*8 + tg + 4)*SB + cc]);
            }
            #pragma unroll
            for (int mi = 0; mi < 4; mi++)
                #pragma unroll
                for (int ni = 0; ni < 4; ni++)
                    asm volatile(
                        "mma.sync.aligned.m16n8k8.row.col.f32.tf32.tf32.f32 "
                        "{%0,%1,%2,%3}, {%4,%5,%6,%7}, {%8,%9}, {%0,%1,%2,%3};"
                        : "+f"(c[mi][ni][0]), "+f"(c[mi][ni][1]),
                          "+f"(c[mi][ni][2]), "+f"(c[mi][ni][3])
                        : "r"(a[mi][0]), "r"(a[mi][1]), "r"(a[mi][2]), "r"(a[mi][3]),
                          "r"(b[ni][0]), "r"(b[ni][1]));
        }
    }

    // epilogue
    #pragma unroll
    for (int mi = 0; mi < 4; mi++) {
        #pragma unroll
        for (int ni = 0; ni < 4; ni++) {
            int row = bm + wm*64 + mi*16 + g;
            int col = bn + wn*32 + ni*8 + tg*2;
            float bx = 0.f, by = 0.f;
            if (BIAS) { float2 bv = *(const float2*)&bias[col]; bx = bv.x; by = bv.y; }
            float v0 = c[mi][ni][0] + bx;
            float v1 = c[mi][ni][1] + by;
            float v2 = c[mi][ni][2] + bx;
            float v3 = c[mi][ni][3] + by;
            if (RELU) {
                v0 = fmaxf(v0, 0.f); v1 = fmaxf(v1, 0.f);
                v2 = fmaxf(v2, 0.f); v3 = fmaxf(v3, 0.f);
            }
            if (RES) {
                const float* rf = (const float*)res;
                float2 r0 = *(const float2*)&rf[(size_t)row*N + col];
                float2 r1 = *(const float2*)&rf[(size_t)(row+8)*N + col];
                v0 += r0.x; v1 += r0.y; v2 += r1.x; v3 += r1.y;
            }
            if (OUTBF16) {
                __nv_bfloat16* Cb = (__nv_bfloat16*)Cm;
                *(__nv_bfloat162*)&Cb[(size_t)row*N + col] =
                    __floats2bfloat162_rn(v0, v1);
                *(__nv_bfloat162*)&Cb[(size_t)(row+8)*N + col] =
                    __floats2bfloat162_rn(v2, v3);
            } else {
                if (CVTOUT) {
                    v0 = f2tf32f(v0); v1 = f2tf32f(v1);
                    v2 = f2tf32f(v2); v3 = f2tf32f(v3);
                }
                float* Cf = (float*)Cm;
                *(float2*)&Cf[(size_t)row*N + col]     = make_float2(v0, v1);
                *(float2*)&Cf[(size_t)(row+8)*N + col] = make_float2(v2, v3);
            }
        }
    }
}

// ---------------- attention scores: warp per token (bf16 h) ------------------
__global__ void __launch_bounds__(256) k_att(const float* __restrict__ att_src,
                                             const float* __restrict__ att_dst) {
    int bt   = blockIdx.x*8 + (threadIdx.x >> 5);
    int lane = threadIdx.x & 31;
    const __nv_bfloat16* hr = g_hb + (size_t)bt*CC;
    #pragma unroll
    for (int hh = 0; hh < HH; hh++) {
        float2 hv = __bfloat1622float2(*(const __nv_bfloat162*)(hr + hh*FF + lane*2));
        float2 as = *(const float2*)(att_src + hh*FF + lane*2);
        float2 ad = *(const float2*)(att_dst + hh*FF + lane*2);
        float ps = hv.x*as.x + hv.y*as.y;
        float pd = hv.x*ad.x + hv.y*ad.y;
        #pragma unroll
        for (int o = 16; o; o >>= 1) {
            ps += __shfl_xor_sync(0xffffffffu, ps, o);
            pd += __shfl_xor_sync(0xffffffffu, pd, o);
        }
        if (lane == 0) {
            g_asrc[bt*HH + hh] = ps;
            g_adst[bt*HH + hh] = pd;
        }
    }
}

// ---------------- GAT aggregate: ONE warp per (b,t), bf16 gather -------------
// Scores |a| < ~1  ->  plain exp(a), no max tracking (math-identical to
// reference's max-subtracted softmax).
// Lanes 0..23 active: j in {0,1}, cols j*192 + lane*8 (8 bf16 = uint4),
// head = 3*j + lane/8. Two independent (acc[8], d) states per lane.
__global__ void __launch_bounds__(256) k_gat(const float* __restrict__ x,
                                             const float* __restrict__ b_gat,
                                             float* __restrict__ x1) {
    int w    = blockIdx.x*8 + (threadIdx.x >> 5);   // bt index in [0,BT)
    int lane = threadIdx.x & 31;
    int t = w % TT;
    int b = w / TT;
    bool active = lane < 24;
    int grp = lane >> 3;                            // 0..2
    int h0 = grp;                                   // j=0 head
    int h1 = 3 + grp;                               // j=1 head

    float adst0 = g_adst[w*HH + h0];
    float adst1 = g_adst[w*HH + h1];

    int beg = g_off[t], end = g_off[t+1];
    const __nv_bfloat16* hbase = g_hb + (size_t)b*TT*CC;
    const float* asrcb = g_asrc + (size_t)b*TT*HH;

    float acc0[8], acc1[8];
    #pragma unroll
    for (int k = 0; k < 8; k++) { acc0[k] = 0.f; acc1[k] = 0.f; }
    float d0 = 0.f, d1 = 0.f;

    int cb = lane*8;

    for (int i = beg; i < end; i++) {
        int s = g_csr_src[i];
        if (active) {
            const __nv_bfloat16* hr = hbase + (size_t)s*CC;
            const float* arow = asrcb + s*HH;

            float a0 = arow[h0] + adst0;
            a0 = (a0 >= 0.f) ? a0 : NSLOPE*a0;
            float w0 = __expf(a0);
            uint4 hv0 = *(const uint4*)(hr + cb);
            {
                float2 f0 = __bfloat1622float2(*(__nv_bfloat162*)&hv0.x);
                float2 f1 = __bfloat1622float2(*(((__nv_bfloat162*)&hv0.x)+1));
                float2 f2 = __bfloat1622float2(*(__nv_bfloat162*)&hv0.z);
                float2 f3 = __bfloat1622float2(*(((__nv_bfloat162*)&hv0.z)+1));
                acc0[0] += w0*f0.x; acc0[1] += w0*f0.y;
                acc0[2] += w0*f1.x; acc0[3] += w0*f1.y;
                acc0[4] += w0*f2.x; acc0[5] += w0*f2.y;
                acc0[6] += w0*f3.x; acc0[7] += w0*f3.y;
            }
            d0 += w0;

            float a1 = arow[h1] + adst1;
            a1 = (a1 >= 0.f) ? a1 : NSLOPE*a1;
            float w1 = __expf(a1);
            uint4 hv1 = *(const uint4*)(hr + 192 + cb);
            {
                float2 f0 = __bfloat1622float2(*(__nv_bfloat162*)&hv1.x);
                float2 f1 = __bfloat1622float2(*(((__nv_bfloat162*)&hv1.x)+1));
                float2 f2 = __bfloat1622float2(*(__nv_bfloat162*)&hv1.z);
                float2 f3 = __bfloat1622float2(*(((__nv_bfloat162*)&hv1.z)+1));
                acc1[0] += w1*f0.x; acc1[1] += w1*f0.y;
                acc1[2] += w1*f1.x; acc1[3] += w1*f1.y;
                acc1[4] += w1*f2.x; acc1[5] += w1*f2.y;
                acc1[6] += w1*f3.x; acc1[7] += w1*f3.y;
            }
            d1 += w1;
        }
    }

    if (active) {
        float inv0 = 1.f/d0, inv1 = 1.f/d1;
        #pragma unroll
        for (int j = 0; j < 2; j++) {
            float* acc = j ? acc1 : acc0;
            float inv = j ? inv1 : inv0;
            int col = j*192 + cb;
            size_t o = (size_t)w*CC + col;
            float4 xv0 = *(const float4*)(x + o);
            float4 xv1 = *(const float4*)(x + o + 4);
            float4 bg0 = *(const float4*)(b_gat + col);
            float4 bg1 = *(const float4*)(b_gat + col + 4);
            float4 r0, r1;
            r0.x = xv0.x + acc[0]*inv + bg0.x;
            r0.y = xv0.y + acc[1]*inv + bg0.y;
            r0.z = xv0.z + acc[2]*inv + bg0.z;
            r0.w = xv0.w + acc[3]*inv + bg0.w;
            r1.x = xv1.x + acc[4]*inv + bg1.x;
            r1.y = xv1.y + acc[5]*inv + bg1.y;
            r1.z = xv1.z + acc[6]*inv + bg1.z;
            r1.w = xv1.w + acc[7]*inv + bg1.w;
            *(float4*)(x1 + o)     = r0;
            *(float4*)(x1 + o + 4) = r1;
        }
    }
}

// ---------------- launch ----------------------------------------------------
extern "C" void kernel_launch(void* const* d_in, const int* in_sizes, int n_in,
                              void* d_out, int out_size) {
    const float* x       = (const float*)d_in[0];
    const int*   ei      = (const int*)  d_in[1];
    const float* W_gat   = (const float*)d_in[2];
    const float* att_src = (const float*)d_in[3];
    const float* att_dst = (const float*)d_in[4];
    const float* b_gat   = (const float*)d_in[5];
    const float* ln1_g   = (const float*)d_in[6];
    const float* ln1_b   = (const float*)d_in[7];
    const float* ln2_g   = (const float*)d_in[8];
    const float* ln2_b   = (const float*)d_in[9];
    const float* W1      = (const float*)d_in[10];
    const float* b1      = (const float*)d_in[11];
    const float* W2      = (const float*)d_in[12];
    const float* b2      = (const float*)d_in[13];
    float* out = (float*)d_out;

    float* p_xn;  cudaGetSymbolAddress((void**)&p_xn,  g_xn);
    void*  p_hb;  cudaGetSymbolAddress(&p_hb,          g_hb);
    float* p_x1;  cudaGetSymbolAddress((void**)&p_x1,  g_x1);
    float* p_h2;  cudaGetSymbolAddress((void**)&p_h2,  g_h2);
    float* p_ffn; cudaGetSymbolAddress((void**)&p_ffn, g_ffn);
    float* p_wg;  cudaGetSymbolAddress((void**)&p_wg,  g_wg_t);
    float* p_w1;  cudaGetSymbolAddress((void**)&p_w1,  g_w1_t);
    float* p_w2;  cudaGetSymbolAddress((void**)&p_w2,  g_w2_t);

    // weight tf32 pre-round (one launch)
    k_cvt_all<<<(NW1+NW2+NW3+255)/256, 256>>>(W_gat, W1, W2);

    // CSR build (shared across batch)
    k_zero_deg<<<(TT+255)/256, 256>>>();
    k_hist<<<(EE+255)/256, 256>>>(ei);
    k_scan<<<1, 1024>>>();
    k_fill<<<(EE+TT+255)/256, 256>>>(ei);

    // LN1 (tf32-rounded output, feeds GEMM1 A)
    k_ln<1><<<BT/8, 256>>>(x, ln1_g, ln1_b, p_xn);

    // GAT projection: h = xn @ W_gat -> bf16   [32768 x 384 x 384]
    k_gemm_tc<0,0,0,0,1><<<dim3(CC/128, BT/128), 256>>>(p_xn, p_wg, nullptr, nullptr,
                                                        p_hb, BT, CC, CC);

    // per-token attention scores (bf16 h)
    k_att<<<BT/8, 256>>>(att_src, att_dst);

    // gather + plain-exp softmax + residual -> x1  (one warp per (b,t))
    k_gat<<<BT/8, 256>>>(x, b_gat, p_x1);

    // LN2 (tf32-rounded output, feeds GEMM2 A)
    k_ln<1><<<BT/8, 256>>>(p_x1, ln2_g, ln2_b, p_h2);

    // MLP: relu(h2 @ W1 + b1) -> ffn (tf32-rounded, feeds GEMM3 A)
    k_gemm_tc<1,1,0,1,0><<<dim3(DFF/128, BT/128), 256>>>(p_h2, p_w1, b1, nullptr,
                                                         p_ffn, BT, DFF, CC);
    // out = ffn @ W2 + b2 + x1          [32768 x 384 x 1536]
    k_gemm_tc<0,1,1,0,0><<<dim3(CC/128, BT/128), 256>>>(p_ffn, p_w2, b2, p_x1,
                                                        out, BT, CC, DFF);
}

// round 10
// speedup vs baseline: 1.4842x; 1.4037x over previous
#include <cuda_runtime.h>
#include <cuda_bf16.h>
#include <stdint.h>
#include <math.h>

#define BB 8
#define TT 4096
#define CC 384
#define HH 6
#define FF 64
#define EE 131072
#define DFF 1536
#define BT (BB*TT)            // 32768
#define NSLOPE 0.2f
#define LNEPS 1e-5f

// ---------------- scratch (device globals; no allocation allowed) ------------
__device__ float g_xn [BT*CC];                // LN1 output (tf32-rounded)
__device__ __nv_bfloat16 g_hb [BT*CC];        // GAT projection h (bf16)
__device__ float g_x1 [BT*CC];                // x + gat_out (fp32, residual)
__device__ __nv_bfloat16 g_h2b[BT*CC];        // LN2 output (bf16, GEMM2 A)
__device__ __nv_bfloat16 g_ffnb[(size_t)BT*DFF]; // MLP hidden (bf16)
__device__ float g_wg_t[CC*CC];               // tf32-rounded W_gat
__device__ __nv_bfloat16 g_w1t[DFF*CC];       // W1^T bf16  [1536][384]
__device__ __nv_bfloat16 g_w2t[CC*DFF];       // W2^T bf16  [384][1536]
__device__ float g_asrc[BT*HH];
__device__ float g_adst[BT*HH];
__device__ int   g_deg [TT];
__device__ int   g_off [TT+1];
__device__ int   g_cur [TT];
__device__ int   g_csr_src[EE+TT];

__device__ __forceinline__ uint32_t f2tf32(float f) {
    uint32_t r;
    asm("cvt.rna.tf32.f32 %0, %1;" : "=r"(r) : "f"(f));
    return r;
}
__device__ __forceinline__ float f2tf32f(float f) {
    return __uint_as_float(f2tf32(f));
}

// ---------------- W_gat tf32 pre-round ---------------------------------------
__global__ void k_cvt_wg(const float* __restrict__ wg) {
    int i = blockIdx.x*blockDim.x + threadIdx.x;
    if (i < CC*CC/4) {
        float4 v = ((const float4*)wg)[i];
        v.x = f2tf32f(v.x); v.y = f2tf32f(v.y);
        v.z = f2tf32f(v.z); v.w = f2tf32f(v.w);
        ((float4*)g_wg_t)[i] = v;
    }
}

// ---------------- weight transpose + bf16 convert: W[K][N] -> WT[N][K] -------
__global__ void k_wt(const float* __restrict__ W, __nv_bfloat16* __restrict__ WT,
                     int K, int N) {
    __shared__ __nv_bfloat16 tile[32][33];
    int n0 = blockIdx.x*32, k0 = blockIdx.y*32;
    int tx = threadIdx.x, ty = threadIdx.y;   // 32 x 8
    #pragma unroll
    for (int r = 0; r < 32; r += 8)
        tile[ty+r][tx] = __float2bfloat16(W[(size_t)(k0+ty+r)*N + n0+tx]);
    __syncthreads();
    #pragma unroll
    for (int r = 0; r < 32; r += 8)
        WT[(size_t)(n0+ty+r)*K + k0+tx] = tile[tx][ty+r];
}

// ---------------- CSR build (per launch; edge list shared across batch) ------
__global__ void k_zero_deg() {
    int i = blockIdx.x*blockDim.x + threadIdx.x;
    if (i < TT) g_deg[i] = 0;
}

__global__ void k_hist(const int* __restrict__ ei) {
    int e = blockIdx.x*blockDim.x + threadIdx.x;
    if (e < EE) atomicAdd(&g_deg[ei[EE + e]], 1);   // dst row
}

__global__ void k_scan() {   // single block, 1024 threads, 4 nodes each
    __shared__ int s[1024];
    int tid  = threadIdx.x;
    int base = tid*4;
    int v0 = g_deg[base+0] + 1;   // +1 self loop
    int v1 = g_deg[base+1] + 1;
    int v2 = g_deg[base+2] + 1;
    int v3 = g_deg[base+3] + 1;
    s[tid] = v0+v1+v2+v3;
    __syncthreads();
    for (int d = 1; d < 1024; d <<= 1) {
        int t = (tid >= d) ? s[tid-d] : 0;
        __syncthreads();
        s[tid] += t;
        __syncthreads();
    }
    int excl = (tid == 0) ? 0 : s[tid-1];
    int o0 = excl, o1 = o0+v0, o2 = o1+v1, o3 = o2+v2;
    g_off[base+0]=o0; g_off[base+1]=o1; g_off[base+2]=o2; g_off[base+3]=o3;
    g_cur[base+0]=o0; g_cur[base+1]=o1; g_cur[base+2]=o2; g_cur[base+3]=o3;
    if (tid == 1023) g_off[TT] = s[1023];
}

__global__ void k_fill(const int* __restrict__ ei) {
    int i = blockIdx.x*blockDim.x + threadIdx.x;
    if (i < EE) {
        int d = ei[EE + i];
        int p = atomicAdd(&g_cur[d], 1);
        g_csr_src[p] = ei[i];                       // src row
    } else if (i < EE + TT) {
        int t = i - EE;
        int p = atomicAdd(&g_cur[t], 1);
        g_csr_src[p] = t;                           // self loop
    }
}

// ---------------- layer norm 1: warp per row, 12 elems/lane ------------------
__global__ void __launch_bounds__(256) k_ln(const float* __restrict__ x,
                                            const float* __restrict__ g,
                                            const float* __restrict__ b,
                                            float* __restrict__ out) {
    int row  = blockIdx.x*8 + (threadIdx.x >> 5);
    int lane = threadIdx.x & 31;
    const float* xr = x + (size_t)row*CC;
    float v[12];
    float sum = 0.f;
    #pragma unroll
    for (int i = 0; i < 12; i++) { v[i] = xr[lane + i*32]; sum += v[i]; }
    #pragma unroll
    for (int o = 16; o; o >>= 1) sum += __shfl_xor_sync(0xffffffffu, sum, o);
    float mu  = sum * (1.f/CC);
    float var = 0.f;
    #pragma unroll
    for (int i = 0; i < 12; i++) { float d = v[i]-mu; var += d*d; }
    #pragma unroll
    for (int o = 16; o; o >>= 1) var += __shfl_xor_sync(0xffffffffu, var, o);
    float rs = rsqrtf(var*(1.f/CC) + LNEPS);
    float* orow = out + (size_t)row*CC;
    #pragma unroll
    for (int i = 0; i < 12; i++) {
        int c = lane + i*32;
        orow[c] = f2tf32f((v[i]-mu)*rs*g[c] + b[c]);
    }
}

// ---------------- tf32 tensor-core GEMM (GEMM1: xn @ W_gat -> h bf16) --------
#define SA 20
#define SB 136
__global__ void __launch_bounds__(256) k_gemm_tf32(const float* __restrict__ A,
                                                   const float* __restrict__ Bm,
                                                   __nv_bfloat16* __restrict__ Cm,
                                                   int M, int N, int K) {
    __shared__ float As[2][128*SA];
    __shared__ float Bs[2][16*SB];

    int tid  = threadIdx.x;
    int lane = tid & 31;
    int w    = tid >> 5;
    int g    = lane >> 2;
    int tg   = lane & 3;
    int wm   = w & 1;
    int wn   = w >> 1;
    int bm   = blockIdx.y * 128;
    int bn   = blockIdx.x * 128;

    float c[4][4][4];
    #pragma unroll
    for (int i = 0; i < 4; i++)
        #pragma unroll
        for (int j = 0; j < 4; j++)
            #pragma unroll
            for (int k = 0; k < 4; k++) c[i][j][k] = 0.f;

    auto loadTile = [&](int k0, int buf) {
        #pragma unroll
        for (int li = 0; li < 2; li++) {
            int idx = tid + 256*li;
            int row = idx >> 2, kc = (idx & 3) * 4;
            uint32_t s = (uint32_t)__cvta_generic_to_shared(&As[buf][row*SA + kc]);
            const float* gp = A + (size_t)(bm + row)*K + k0 + kc;
            asm volatile("cp.async.cg.shared.global [%0], [%1], 16;\n" :: "r"(s), "l"(gp));
        }
        #pragma unroll
        for (int li = 0; li < 2; li++) {
            int idx = tid + 256*li;
            int kr = idx >> 5, nc = (idx & 31) * 4;
            uint32_t s = (uint32_t)__cvta_generic_to_shared(&Bs[buf][kr*SB + nc]);
            const float* gp = Bm + (size_t)(k0 + kr)*N + bn + nc;
            asm volatile("cp.async.cg.shared.global [%0], [%1], 16;\n" :: "r"(s), "l"(gp));
        }
        asm volatile("cp.async.commit_group;\n");
    };

    int nk = K / 16;
    loadTile(0, 0);

    for (int i = 0; i < nk; i++) {
        int cur = i & 1;
        asm volatile("cp.async.wait_group 0;\n" ::: "memory");
        __syncthreads();
        if (i + 1 < nk) loadTile((i + 1)*16, (i + 1) & 1);

        const float* Ab = &As[cur][0];
        const float* Bb = &Bs[cur][0];
        #pragma unroll
        for (int ks = 0; ks < 2; ks++) {
            uint32_t a[4][4], b[4][2];
            #pragma unroll
            for (int mi = 0; mi < 4; mi++) {
                int r0 = wm*64 + mi*16 + g;
                a[mi][0] = __float_as_uint(Ab[ r0    *SA + ks*8 + tg    ]);
                a[mi][1] = __float_as_uint(Ab[(r0+8) *SA + ks*8 + tg    ]);
                a[mi][2] = __float_as_uint(Ab[ r0    *SA + ks*8 + tg + 4]);
                a[mi][3] = __float_as_uint(Ab[(r0+8) *SA + ks*8 + tg + 4]);
            }
            #pragma unroll
            for (int ni = 0; ni < 4; ni++) {
                int cc = wn*32 + ni*8 + g;
                b[ni][0] = __float_as_uint(Bb[(ks*8 + tg    )*SB + cc]);
                b[ni][1] = __float_as_uint(Bb[(ks*8 + tg + 4)*SB + cc]);
            }
            #pragma unroll
            for (int mi = 0; mi < 4; mi++)
                #pragma unroll
                for (int ni = 0; ni < 4; ni++)
                    asm volatile(
                        "mma.sync.aligned.m16n8k8.row.col.f32.tf32.tf32.f32 "
                        "{%0,%1,%2,%3}, {%4,%5,%6,%7}, {%8,%9}, {%0,%1,%2,%3};"
                        : "+f"(c[mi][ni][0]), "+f"(c[mi][ni][1]),
                          "+f"(c[mi][ni][2]), "+f"(c[mi][ni][3])
                        : "r"(a[mi][0]), "r"(a[mi][1]), "r"(a[mi][2]), "r"(a[mi][3]),
                          "r"(b[ni][0]), "r"(b[ni][1]));
        }
    }

    #pragma unroll
    for (int mi = 0; mi < 4; mi++) {
        #pragma unroll
        for (int ni = 0; ni < 4; ni++) {
            int row = bm + wm*64 + mi*16 + g;
            int col = bn + wn*32 + ni*8 + tg*2;
            *(__nv_bfloat162*)&Cm[(size_t)row*N + col] =
                __floats2bfloat162_rn(c[mi][ni][0], c[mi][ni][1]);
            *(__nv_bfloat162*)&Cm[(size_t)(row+8)*N + col] =
                __floats2bfloat162_rn(c[mi][ni][2], c[mi][ni][3]);
        }
    }
}

// ---------------- bf16 tensor-core GEMM (MLP) --------------------------------
// C[MxN] = A[MxK](bf16,row) @ BT[NxK](bf16,row = B col-major)
// mma.m16n8k16.bf16, block 128x128x32, 8 warps (2m x 4n), warp 64x32.
#define SW 40   // smem row stride in bf16 (32 + 8 pad) -> conflict-free frags

template<int RELU, int RES, int OUTBF16>
__global__ void __launch_bounds__(256) k_gemm_bf(const __nv_bfloat16* __restrict__ A,
                                                 const __nv_bfloat16* __restrict__ Bt,
                                                 const float* __restrict__ bias,
                                                 const float* __restrict__ res,
                                                 void* __restrict__ Cm,
                                                 int M, int N, int K) {
    __shared__ __nv_bfloat16 As[2][128*SW];
    __shared__ __nv_bfloat16 Bs[2][128*SW];

    int tid  = threadIdx.x;
    int lane = tid & 31;
    int w    = tid >> 5;
    int g    = lane >> 2;
    int tg   = lane & 3;
    int wm   = w & 1;
    int wn   = w >> 1;
    int bm   = blockIdx.y * 128;
    int bn   = blockIdx.x * 128;

    float c[4][4][4];
    #pragma unroll
    for (int i = 0; i < 4; i++)
        #pragma unroll
        for (int j = 0; j < 4; j++)
            #pragma unroll
            for (int k = 0; k < 4; k++) c[i][j][k] = 0.f;

    auto loadTile = [&](int k0, int buf) {
        #pragma unroll
        for (int li = 0; li < 2; li++) {          // A: 128 rows x 32 bf16
            int idx = tid + 256*li;
            int row = idx >> 2, kc = (idx & 3) * 8;
            uint32_t s = (uint32_t)__cvta_generic_to_shared(&As[buf][row*SW + kc]);
            const __nv_bfloat16* gp = A + (size_t)(bm + row)*K + k0 + kc;
            asm volatile("cp.async.cg.shared.global [%0], [%1], 16;\n" :: "r"(s), "l"(gp));
        }
        #pragma unroll
        for (int li = 0; li < 2; li++) {          // B^T: 128 n-rows x 32 bf16
            int idx = tid + 256*li;
            int row = idx >> 2, kc = (idx & 3) * 8;
            uint32_t s = (uint32_t)__cvta_generic_to_shared(&Bs[buf][row*SW + kc]);
            const __nv_bfloat16* gp = Bt + (size_t)(bn + row)*K + k0 + kc;
            asm volatile("cp.async.cg.shared.global [%0], [%1], 16;\n" :: "r"(s), "l"(gp));
        }
        asm volatile("cp.async.commit_group;\n");
    };

    int nk = K / 32;
    loadTile(0, 0);

    for (int i = 0; i < nk; i++) {
        int cur = i & 1;
        asm volatile("cp.async.wait_group 0;\n" ::: "memory");
        __syncthreads();
        if (i + 1 < nk) loadTile((i + 1)*32, (i + 1) & 1);

        const __nv_bfloat16* Ab = &As[cur][0];
        const __nv_bfloat16* Bb = &Bs[cur][0];
        #pragma unroll
        for (int kk = 0; kk < 2; kk++) {          // two k16 chunks
            uint32_t a[4][4], b[4][2];
            #pragma unroll
            for (int mi = 0; mi < 4; mi++) {
                int r0 = wm*64 + mi*16 + g;
                a[mi][0] = *(const uint32_t*)&Ab[ r0    *SW + kk*16 + 2*tg    ];
                a[mi][1] = *(const uint32_t*)&Ab[(r0+8) *SW + kk*16 + 2*tg    ];
                a[mi][2] = *(const uint32_t*)&Ab[ r0    *SW + kk*16 + 2*tg + 8];
                a[mi][3] = *(const uint32_t*)&Ab[(r0+8) *SW + kk*16 + 2*tg + 8];
            }
            #pragma unroll
            for (int ni = 0; ni < 4; ni++) {
                int n0 = wn*32 + ni*8 + g;
                b[ni][0] = *(const uint32_t*)&Bb[n0*SW + kk*16 + 2*tg    ];
                b[ni][1] = *(const uint32_t*)&Bb[n0*SW + kk*16 + 2*tg + 8];
            }
            #pragma unroll
            for (int mi = 0; mi < 4; mi++)
                #pragma unroll
                for (int ni = 0; ni < 4; ni++)
                    asm volatile(
                        "mma.sync.aligned.m16n8k16.row.col.f32.bf16.bf16.f32 "
                        "{%0,%1,%2,%3}, {%4,%5,%6,%7}, {%8,%9}, {%0,%1,%2,%3};"
                        : "+f"(c[mi][ni][0]), "+f"(c[mi][ni][1]),
                          "+f"(c[mi][ni][2]), "+f"(c[mi][ni][3])
                        : "r"(a[mi][0]), "r"(a[mi][1]), "r"(a[mi][2]), "r"(a[mi][3]),
                          "r"(b[ni][0]), "r"(b[ni][1]));
        }
    }

    #pragma unroll
    for (int mi = 0; mi < 4; mi++) {
        #pragma unroll
        for (int ni = 0; ni < 4; ni++) {
            int row = bm + wm*64 + mi*16 + g;
            int col = bn + wn*32 + ni*8 + tg*2;
            float2 bv = *(const float2*)&bias[col];
            float v0 = c[mi][ni][0] + bv.x;
            float v1 = c[mi][ni][1] + bv.y;
            float v2 = c[mi][ni][2] + bv.x;
            float v3 = c[mi][ni][3] + bv.y;
            if (RELU) {
                v0 = fmaxf(v0, 0.f); v1 = fmaxf(v1, 0.f);
                v2 = fmaxf(v2, 0.f); v3 = fmaxf(v3, 0.f);
            }
            if (RES) {
                float2 r0 = *(const float2*)&res[(size_t)row*N + col];
                float2 r1 = *(const float2*)&res[(size_t)(row+8)*N + col];
                v0 += r0.x; v1 += r0.y; v2 += r1.x; v3 += r1.y;
            }
            if (OUTBF16) {
                __nv_bfloat16* Cb = (__nv_bfloat16*)Cm;
                *(__nv_bfloat162*)&Cb[(size_t)row*N + col] =
                    __floats2bfloat162_rn(v0, v1);
                *(__nv_bfloat162*)&Cb[(size_t)(row+8)*N + col] =
                    __floats2bfloat162_rn(v2, v3);
            } else {
                float* Cf = (float*)Cm;
                *(float2*)&Cf[(size_t)row*N + col]     = make_float2(v0, v1);
                *(float2*)&Cf[(size_t)(row+8)*N + col] = make_float2(v2, v3);
            }
        }
    }
}

// ---------------- attention scores: warp per token (bf16 h) ------------------
__global__ void __launch_bounds__(256) k_att(const float* __restrict__ att_src,
                                             const float* __restrict__ att_dst) {
    int bt   = blockIdx.x*8 + (threadIdx.x >> 5);
    int lane = threadIdx.x & 31;
    const __nv_bfloat16* hr = g_hb + (size_t)bt*CC;
    #pragma unroll
    for (int hh = 0; hh < HH; hh++) {
        float2 hv = __bfloat1622float2(*(const __nv_bfloat162*)(hr + hh*FF + lane*2));
        float2 as = *(const float2*)(att_src + hh*FF + lane*2);
        float2 ad = *(const float2*)(att_dst + hh*FF + lane*2);
        float ps = hv.x*as.x + hv.y*as.y;
        float pd = hv.x*ad.x + hv.y*ad.y;
        #pragma unroll
        for (int o = 16; o; o >>= 1) {
            ps += __shfl_xor_sync(0xffffffffu, ps, o);
            pd += __shfl_xor_sync(0xffffffffu, pd, o);
        }
        if (lane == 0) {
            g_asrc[bt*HH + hh] = ps;
            g_adst[bt*HH + hh] = pd;
        }
    }
}

// ---------------- GAT aggregate + fused LN2: ONE warp per (b,t) --------------
// Lanes 0..23 active: j in {0,1}, cols j*192 + lane*8 (uint4 of bf16),
// head = 3*j + lane/8. Plain exp(a) (|a| small -> identical to max-softmax).
// After aggregation the warp holds the full 384-wide x1 row -> LN2 in-warp,
// writes x1 (fp32 residual) and h2 (bf16, GEMM2 A).
__global__ void __launch_bounds__(256) k_gat(const float* __restrict__ x,
                                             const float* __restrict__ b_gat,
                                             const float* __restrict__ ln2g,
                                             const float* __restrict__ ln2b,
                                             float* __restrict__ x1,
                                             __nv_bfloat16* __restrict__ h2b) {
    int w    = blockIdx.x*8 + (threadIdx.x >> 5);   // bt index
    int lane = threadIdx.x & 31;
    int t = w % TT;
    int b = w / TT;
    bool active = lane < 24;
    int grp = lane >> 3;
    int h0 = grp;
    int h1 = 3 + grp;
    int cb = lane*8;

    float adst0 = active ? g_adst[w*HH + h0] : 0.f;
    float adst1 = active ? g_adst[w*HH + h1] : 0.f;

    int beg = g_off[t], end = g_off[t+1];
    const __nv_bfloat16* hbase = g_hb + (size_t)b*TT*CC;
    const float* asrcb = g_asrc + (size_t)b*TT*HH;

    float acc0[8], acc1[8];
    #pragma unroll
    for (int k = 0; k < 8; k++) { acc0[k] = 0.f; acc1[k] = 0.f; }
    float d0 = 0.f, d1 = 0.f;

    for (int i = beg; i < end; i++) {
        int s = g_csr_src[i];
        if (active) {
            const __nv_bfloat16* hr = hbase + (size_t)s*CC;
            const float* arow = asrcb + s*HH;

            float a0 = arow[h0] + adst0;
            a0 = (a0 >= 0.f) ? a0 : NSLOPE*a0;
            float w0 = __expf(a0);
            uint4 hv0 = *(const uint4*)(hr + cb);
            {
                float2 f0 = __bfloat1622float2(*(__nv_bfloat162*)&hv0.x);
                float2 f1 = __bfloat1622float2(*(((__nv_bfloat162*)&hv0.x)+1));
                float2 f2 = __bfloat1622float2(*(__nv_bfloat162*)&hv0.z);
                float2 f3 = __bfloat1622float2(*(((__nv_bfloat162*)&hv0.z)+1));
                acc0[0] += w0*f0.x; acc0[1] += w0*f0.y;
                acc0[2] += w0*f1.x; acc0[3] += w0*f1.y;
                acc0[4] += w0*f2.x; acc0[5] += w0*f2.y;
                acc0[6] += w0*f3.x; acc0[7] += w0*f3.y;
            }
            d0 += w0;

            float a1 = arow[h1] + adst1;
            a1 = (a1 >= 0.f) ? a1 : NSLOPE*a1;
            float w1 = __expf(a1);
            uint4 hv1 = *(const uint4*)(hr + 192 + cb);
            {
                float2 f0 = __bfloat1622float2(*(__nv_bfloat162*)&hv1.x);
                float2 f1 = __bfloat1622float2(*(((__nv_bfloat162*)&hv1.x)+1));
                float2 f2 = __bfloat1622float2(*(__nv_bfloat162*)&hv1.z);
                float2 f3 = __bfloat1622float2(*(((__nv_bfloat162*)&hv1.z)+1));
                acc1[0] += w1*f0.x; acc1[1] += w1*f0.y;
                acc1[2] += w1*f1.x; acc1[3] += w1*f1.y;
                acc1[4] += w1*f2.x; acc1[5] += w1*f2.y;
                acc1[6] += w1*f3.x; acc1[7] += w1*f3.y;
            }
            d1 += w1;
        }
    }

    // x1 row values (16 per active lane) + row sum
    float vals[16];
    float sum = 0.f;
    if (active) {
        float inv0 = 1.f/d0, inv1 = 1.f/d1;
        #pragma unroll
        for (int j = 0; j < 2; j++) {
            float* acc = j ? acc1 : acc0;
            float inv = j ? inv1 : inv0;
            int col = j*192 + cb;
            size_t o = (size_t)w*CC + col;
            float4 xv0 = *(const float4*)(x + o);
            float4 xv1 = *(const float4*)(x + o + 4);
            float4 bg0 = *(const float4*)(b_gat + col);
            float4 bg1 = *(const float4*)(b_gat + col + 4);
            vals[j*8+0] = xv0.x + acc[0]*inv + bg0.x;
            vals[j*8+1] = xv0.y + acc[1]*inv + bg0.y;
            vals[j*8+2] = xv0.z + acc[2]*inv + bg0.z;
            vals[j*8+3] = xv0.w + acc[3]*inv + bg0.w;
            vals[j*8+4] = xv1.x + acc[4]*inv + bg1.x;
            vals[j*8+5] = xv1.y + acc[5]*inv + bg1.y;
            vals[j*8+6] = xv1.z + acc[6]*inv + bg1.z;
            vals[j*8+7] = xv1.w + acc[7]*inv + bg1.w;
        }
        #pragma unroll
        for (int k = 0; k < 16; k++) sum += vals[k];
    }
    #pragma unroll
    for (int o = 16; o; o >>= 1) sum += __shfl_xor_sync(0xffffffffu, sum, o);
    float mu = sum * (1.f/CC);
    float sq = 0.f;
    if (active) {
        #pragma unroll
        for (int k = 0; k < 16; k++) { float dd = vals[k]-mu; sq += dd*dd; }
    }
    #pragma unroll
    for (int o = 16; o; o >>= 1) sq += __shfl_xor_sync(0xffffffffu, sq, o);
    float rs = rsqrtf(sq*(1.f/CC) + LNEPS);

    if (active) {
        #pragma unroll
        for (int j = 0; j < 2; j++) {
            int col = j*192 + cb;
            size_t o = (size_t)w*CC + col;
            // x1 (fp32 residual)
            float4 r0 = make_float4(vals[j*8+0], vals[j*8+1], vals[j*8+2], vals[j*8+3]);
            float4 r1 = make_float4(vals[j*8+4], vals[j*8+5], vals[j*8+6], vals[j*8+7]);
            *(float4*)(x1 + o)     = r0;
            *(float4*)(x1 + o + 4) = r1;
            // h2 = LN2(x1) in bf16
            float4 g0 = *(const float4*)(ln2g + col);
            float4 g1 = *(const float4*)(ln2g + col + 4);
            float4 bb0 = *(const float4*)(ln2b + col);
            float4 bb1 = *(const float4*)(ln2b + col + 4);
            uint4 hv;
            __nv_bfloat162* hp = (__nv_bfloat162*)&hv;
            hp[0] = __floats2bfloat162_rn((r0.x-mu)*rs*g0.x + bb0.x,
                                          (r0.y-mu)*rs*g0.y + bb0.y);
            hp[1] = __floats2bfloat162_rn((r0.z-mu)*rs*g0.z + bb0.z,
                                          (r0.w-mu)*rs*g0.w + bb0.w);
            hp[2] = __floats2bfloat162_rn((r1.x-mu)*rs*g1.x + bb1.x,
                                          (r1.y-mu)*rs*g1.y + bb1.y);
            hp[3] = __floats2bfloat162_rn((r1.z-mu)*rs*g1.z + bb1.z,
                                          (r1.w-mu)*rs*g1.w + bb1.w);
            *(uint4*)(h2b + o) = hv;
        }
    }
}

// ---------------- launch ----------------------------------------------------
extern "C" void kernel_launch(void* const* d_in, const int* in_sizes, int n_in,
                              void* d_out, int out_size) {
    const float* x       = (const float*)d_in[0];
    const int*   ei      = (const int*)  d_in[1];
    const float* W_gat   = (const float*)d_in[2];
    const float* att_src = (const float*)d_in[3];
    const float* att_dst = (const float*)d_in[4];
    const float* b_gat   = (const float*)d_in[5];
    const float* ln1_g   = (const float*)d_in[6];
    const float* ln1_b   = (const float*)d_in[7];
    const float* ln2_g   = (const float*)d_in[8];
    const float* ln2_b   = (const float*)d_in[9];
    const float* W1      = (const float*)d_in[10];
    const float* b1      = (const float*)d_in[11];
    const float* W2      = (const float*)d_in[12];
    const float* b2      = (const float*)d_in[13];
    float* out = (float*)d_out;

    float* p_xn;  cudaGetSymbolAddress((void**)&p_xn,  g_xn);
    __nv_bfloat16* p_hb;  cudaGetSymbolAddress((void**)&p_hb,  g_hb);
    float* p_x1;  cudaGetSymbolAddress((void**)&p_x1,  g_x1);
    __nv_bfloat16* p_h2b; cudaGetSymbolAddress((void**)&p_h2b, g_h2b);
    __nv_bfloat16* p_ffnb;cudaGetSymbolAddress((void**)&p_ffnb,g_ffnb);
    float* p_wg;  cudaGetSymbolAddress((void**)&p_wg,  g_wg_t);
    __nv_bfloat16* p_w1t; cudaGetSymbolAddress((void**)&p_w1t, g_w1t);
    __nv_bfloat16* p_w2t; cudaGetSymbolAddress((void**)&p_w2t, g_w2t);

    // weight prep
    k_cvt_wg<<<(CC*CC/4+255)/256, 256>>>(W_gat);
    k_wt<<<dim3(DFF/32, CC/32), dim3(32,8)>>>(W1, p_w1t, CC, DFF);   // W1^T [1536][384]
    k_wt<<<dim3(CC/32, DFF/32), dim3(32,8)>>>(W2, p_w2t, DFF, CC);   // W2^T [384][1536]

    // CSR build (shared across batch)
    k_zero_deg<<<(TT+255)/256, 256>>>();
    k_hist<<<(EE+255)/256, 256>>>(ei);
    k_scan<<<1, 1024>>>();
    k_fill<<<(EE+TT+255)/256, 256>>>(ei);

    // LN1 (tf32-rounded, feeds GEMM1 A)
    k_ln<<<BT/8, 256>>>(x, ln1_g, ln1_b, p_xn);

    // GEMM1 (tf32): h = xn @ W_gat -> bf16
    k_gemm_tf32<<<dim3(CC/128, BT/128), 256>>>(p_xn, p_wg, p_hb, BT, CC, CC);

    // attention scores
    k_att<<<BT/8, 256>>>(att_src, att_dst);

    // gather + softmax + residual + fused LN2 -> x1 (fp32), h2 (bf16)
    k_gat<<<BT/8, 256>>>(x, b_gat, ln2_g, ln2_b, p_x1, p_h2b);

    // GEMM2 (bf16): ffn = relu(h2 @ W1 + b1) -> bf16
    k_gemm_bf<1,0,1><<<dim3(DFF/128, BT/128), 256>>>(p_h2b, p_w1t, b1, nullptr,
                                                     p_ffnb, BT, DFF, CC);
    // GEMM3 (bf16): out = ffn @ W2 + b2 + x1 -> fp32
    k_gemm_bf<0,1,0><<<dim3(CC/128, BT/128), 256>>>(p_ffnb, p_w2t, b2, p_x1,
                                                    out, BT, CC, DFF);
}

// round 11
// speedup vs baseline: 1.5915x; 1.0723x over previous
#include <cuda_runtime.h>
#include <cuda_bf16.h>
#include <stdint.h>
#include <math.h>

#define BB 8
#define TT 4096
#define CC 384
#define HH 6
#define FF 64
#define EE 131072
#define DFF 1536
#define BT (BB*TT)            // 32768
#define NSLOPE 0.2f
#define LNEPS 1e-5f

// ---------------- scratch (device globals; no allocation allowed) ------------
__device__ float g_xn [BT*CC];                // LN1 output (tf32-rounded)
__device__ __nv_bfloat16 g_hb [BT*CC];        // GAT projection h (bf16)
__device__ float g_x1 [BT*CC];                // x + gat_out (fp32, residual)
__device__ __nv_bfloat16 g_h2b[BT*CC];        // LN2 output (bf16, GEMM2 A)
__device__ __nv_bfloat16 g_ffnb[(size_t)BT*DFF]; // MLP hidden (bf16)
__device__ float g_wg_t[CC*CC];               // tf32-rounded W_gat
__device__ __nv_bfloat16 g_w1t[DFF*CC];       // W1^T bf16  [1536][384]
__device__ __nv_bfloat16 g_w2t[CC*DFF];       // W2^T bf16  [384][1536]
__device__ float g_asrc[BT*HH];
__device__ float g_adst[BT*HH];
__device__ int   g_deg [TT];
__device__ int   g_off [TT+1];
__device__ int   g_cur [TT];
__device__ int   g_csr_src[EE+TT];

__device__ __forceinline__ uint32_t f2tf32(float f) {
    uint32_t r;
    asm("cvt.rna.tf32.f32 %0, %1;" : "=r"(r) : "f"(f));
    return r;
}
__device__ __forceinline__ float f2tf32f(float f) {
    return __uint_as_float(f2tf32(f));
}

#define LDSM4(r0,r1,r2,r3,addr) \
    asm volatile("ldmatrix.sync.aligned.m8n8.x4.shared.b16 {%0,%1,%2,%3}, [%4];" \
        : "=r"(r0), "=r"(r1), "=r"(r2), "=r"(r3) : "r"(addr))

// ---------------- W_gat tf32 pre-round ---------------------------------------
__global__ void k_cvt_wg(const float* __restrict__ wg) {
    int i = blockIdx.x*blockDim.x + threadIdx.x;
    if (i < CC*CC/4) {
        float4 v = ((const float4*)wg)[i];
        v.x = f2tf32f(v.x); v.y = f2tf32f(v.y);
        v.z = f2tf32f(v.z); v.w = f2tf32f(v.w);
        ((float4*)g_wg_t)[i] = v;
    }
}

// ---------------- weight transpose + bf16: both W1 and W2 in one launch ------
#define NB1 ((DFF/32)*(CC/32))   // 48*12 = 576 blocks for W1^T
#define NB2 ((CC/32)*(DFF/32))   // 576 blocks for W2^T
__global__ void k_wt_both(const float* __restrict__ W1f,
                          const float* __restrict__ W2f) {
    __shared__ __nv_bfloat16 tile[32][33];
    int bid = blockIdx.x;
    const float* W; __nv_bfloat16* WT; int K, N, bx, by;
    if (bid < NB1) { W = W1f; WT = g_w1t; K = CC;  N = DFF;
                     bx = bid % (DFF/32); by = bid / (DFF/32); }
    else           { bid -= NB1; W = W2f; WT = g_w2t; K = DFF; N = CC;
                     bx = bid % (CC/32);  by = bid / (CC/32); }
    int n0 = bx*32, k0 = by*32;
    int tx = threadIdx.x, ty = threadIdx.y;   // 32 x 8
    #pragma unroll
    for (int r = 0; r < 32; r += 8)
        tile[ty+r][tx] = __float2bfloat16(W[(size_t)(k0+ty+r)*N + n0+tx]);
    __syncthreads();
    #pragma unroll
    for (int r = 0; r < 32; r += 8)
        WT[(size_t)(n0+ty+r)*K + k0+tx] = tile[tx][ty+r];
}

// ---------------- CSR build (per launch; edge list shared across batch) ------
__global__ void k_zero_deg() {
    int i = blockIdx.x*blockDim.x + threadIdx.x;
    if (i < TT) g_deg[i] = 0;
}

__global__ void k_hist(const int* __restrict__ ei) {
    int e = blockIdx.x*blockDim.x + threadIdx.x;
    if (e < EE) atomicAdd(&g_deg[ei[EE + e]], 1);   // dst row
}

__global__ void k_scan() {   // single block, 1024 threads, 4 nodes each
    __shared__ int s[1024];
    int tid  = threadIdx.x;
    int base = tid*4;
    int v0 = g_deg[base+0] + 1;   // +1 self loop
    int v1 = g_deg[base+1] + 1;
    int v2 = g_deg[base+2] + 1;
    int v3 = g_deg[base+3] + 1;
    s[tid] = v0+v1+v2+v3;
    __syncthreads();
    for (int d = 1; d < 1024; d <<= 1) {
        int t = (tid >= d) ? s[tid-d] : 0;
        __syncthreads();
        s[tid] += t;
        __syncthreads();
    }
    int excl = (tid == 0) ? 0 : s[tid-1];
    int o0 = excl, o1 = o0+v0, o2 = o1+v1, o3 = o2+v2;
    g_off[base+0]=o0; g_off[base+1]=o1; g_off[base+2]=o2; g_off[base+3]=o3;
    g_cur[base+0]=o0; g_cur[base+1]=o1; g_cur[base+2]=o2; g_cur[base+3]=o3;
    if (tid == 1023) g_off[TT] = s[1023];
}

__global__ void k_fill(const int* __restrict__ ei) {
    int i = blockIdx.x*blockDim.x + threadIdx.x;
    if (i < EE) {
        int d = ei[EE + i];
        int p = atomicAdd(&g_cur[d], 1);
        g_csr_src[p] = ei[i];                       // src row
    } else if (i < EE + TT) {
        int t = i - EE;
        int p = atomicAdd(&g_cur[t], 1);
        g_csr_src[p] = t;                           // self loop
    }
}

// ---------------- layer norm 1: warp per row, 12 elems/lane ------------------
__global__ void __launch_bounds__(256) k_ln(const float* __restrict__ x,
                                            const float* __restrict__ g,
                                            const float* __restrict__ b,
                                            float* __restrict__ out) {
    int row  = blockIdx.x*8 + (threadIdx.x >> 5);
    int lane = threadIdx.x & 31;
    const float* xr = x + (size_t)row*CC;
    float v[12];
    float sum = 0.f;
    #pragma unroll
    for (int i = 0; i < 12; i++) { v[i] = xr[lane + i*32]; sum += v[i]; }
    #pragma unroll
    for (int o = 16; o; o >>= 1) sum += __shfl_xor_sync(0xffffffffu, sum, o);
    float mu  = sum * (1.f/CC);
    float var = 0.f;
    #pragma unroll
    for (int i = 0; i < 12; i++) { float d = v[i]-mu; var += d*d; }
    #pragma unroll
    for (int o = 16; o; o >>= 1) var += __shfl_xor_sync(0xffffffffu, var, o);
    float rs = rsqrtf(var*(1.f/CC) + LNEPS);
    float* orow = out + (size_t)row*CC;
    #pragma unroll
    for (int i = 0; i < 12; i++) {
        int c = lane + i*32;
        orow[c] = f2tf32f((v[i]-mu)*rs*g[c] + b[c]);
    }
}

// ---------------- tf32 tensor-core GEMM (GEMM1: xn @ W_gat -> h bf16) --------
#define SA 20
#define SB 136
__global__ void __launch_bounds__(256) k_gemm_tf32(const float* __restrict__ A,
                                                   const float* __restrict__ Bm,
                                                   __nv_bfloat16* __restrict__ Cm,
                                                   int M, int N, int K) {
    __shared__ float As[2][128*SA];
    __shared__ float Bs[2][16*SB];

    int tid  = threadIdx.x;
    int lane = tid & 31;
    int w    = tid >> 5;
    int g    = lane >> 2;
    int tg   = lane & 3;
    int wm   = w & 1;
    int wn   = w >> 1;
    int bm   = blockIdx.y * 128;
    int bn   = blockIdx.x * 128;

    float c[4][4][4];
    #pragma unroll
    for (int i = 0; i < 4; i++)
        #pragma unroll
        for (int j = 0; j < 4; j++)
            #pragma unroll
            for (int k = 0; k < 4; k++) c[i][j][k] = 0.f;

    auto loadTile = [&](int k0, int buf) {
        #pragma unroll
        for (int li = 0; li < 2; li++) {
            int idx = tid + 256*li;
            int row = idx >> 2, kc = (idx & 3) * 4;
            uint32_t s = (uint32_t)__cvta_generic_to_shared(&As[buf][row*SA + kc]);
            const float* gp = A + (size_t)(bm + row)*K + k0 + kc;
            asm volatile("cp.async.cg.shared.global [%0], [%1], 16;\n" :: "r"(s), "l"(gp));
        }
        #pragma unroll
        for (int li = 0; li < 2; li++) {
            int idx = tid + 256*li;
            int kr = idx >> 5, nc = (idx & 31) * 4;
            uint32_t s = (uint32_t)__cvta_generic_to_shared(&Bs[buf][kr*SB + nc]);
            const float* gp = Bm + (size_t)(k0 + kr)*N + bn + nc;
            asm volatile("cp.async.cg.shared.global [%0], [%1], 16;\n" :: "r"(s), "l"(gp));
        }
        asm volatile("cp.async.commit_group;\n");
    };

    int nk = K / 16;
    loadTile(0, 0);

    for (int i = 0; i < nk; i++) {
        int cur = i & 1;
        asm volatile("cp.async.wait_group 0;\n" ::: "memory");
        __syncthreads();
        if (i + 1 < nk) loadTile((i + 1)*16, (i + 1) & 1);

        const float* Ab = &As[cur][0];
        const float* Bb = &Bs[cur][0];
        #pragma unroll
        for (int ks = 0; ks < 2; ks++) {
            uint32_t a[4][4], b[4][2];
            #pragma unroll
            for (int mi = 0; mi < 4; mi++) {
                int r0 = wm*64 + mi*16 + g;
                a[mi][0] = __float_as_uint(Ab[ r0    *SA + ks*8 + tg    ]);
                a[mi][1] = __float_as_uint(Ab[(r0+8) *SA + ks*8 + tg    ]);
                a[mi][2] = __float_as_uint(Ab[ r0    *SA + ks*8 + tg + 4]);
                a[mi][3] = __float_as_uint(Ab[(r0+8) *SA + ks*8 + tg + 4]);
            }
            #pragma unroll
            for (int ni = 0; ni < 4; ni++) {
                int cc = wn*32 + ni*8 + g;
                b[ni][0] = __float_as_uint(Bb[(ks*8 + tg    )*SB + cc]);
                b[ni][1] = __float_as_uint(Bb[(ks*8 + tg + 4)*SB + cc]);
            }
            #pragma unroll
            for (int mi = 0; mi < 4; mi++)
                #pragma unroll
                for (int ni = 0; ni < 4; ni++)
                    asm volatile(
                        "mma.sync.aligned.m16n8k8.row.col.f32.tf32.tf32.f32 "
                        "{%0,%1,%2,%3}, {%4,%5,%6,%7}, {%8,%9}, {%0,%1,%2,%3};"
                        : "+f"(c[mi][ni][0]), "+f"(c[mi][ni][1]),
                          "+f"(c[mi][ni][2]), "+f"(c[mi][ni][3])
                        : "r"(a[mi][0]), "r"(a[mi][1]), "r"(a[mi][2]), "r"(a[mi][3]),
                          "r"(b[ni][0]), "r"(b[ni][1]));
        }
    }

    #pragma unroll
    for (int mi = 0; mi < 4; mi++) {
        #pragma unroll
        for (int ni = 0; ni < 4; ni++) {
            int row = bm + wm*64 + mi*16 + g;
            int col = bn + wn*32 + ni*8 + tg*2;
            *(__nv_bfloat162*)&Cm[(size_t)row*N + col] =
                __floats2bfloat162_rn(c[mi][ni][0], c[mi][ni][1]);
            *(__nv_bfloat162*)&Cm[(size_t)(row+8)*N + col] =
                __floats2bfloat162_rn(c[mi][ni][2], c[mi][ni][3]);
        }
    }
}

// ---------------- bf16 tensor-core GEMM (MLP), ldmatrix fragments ------------
// C[MxN] = A[MxK](bf16,row) @ BT[NxK](bf16,row = B col-major)
// mma.m16n8k16.bf16, block 128x128x32, 8 warps (2m x 4n), warp 64x32.
#define SW 40   // smem row stride in bf16 (32 + 8 pad); 80B rows, LDSM-conflict-free
#define ABUF (128*SW*2)   // bytes per A/B buffer

template<int RELU, int RES, int OUTBF16>
__global__ void __launch_bounds__(256) k_gemm_bf(const __nv_bfloat16* __restrict__ A,
                                                 const __nv_bfloat16* __restrict__ Bt,
                                                 const float* __restrict__ bias,
                                                 const float* __restrict__ res,
                                                 void* __restrict__ Cm,
                                                 int M, int N, int K) {
    __shared__ __nv_bfloat16 As[2][128*SW];
    __shared__ __nv_bfloat16 Bs[2][128*SW];

    int tid  = threadIdx.x;
    int lane = tid & 31;
    int w    = tid >> 5;
    int g    = lane >> 2;
    int tg   = lane & 3;
    int wm   = w & 1;
    int wn   = w >> 1;
    int bm   = blockIdx.y * 128;
    int bn   = blockIdx.x * 128;

    // ldmatrix per-lane address offsets (bytes), before kk/buffer terms
    int mrow = lane & 7;
    int msel = lane >> 3;
    uint32_t As0 = (uint32_t)__cvta_generic_to_shared(&As[0][0]);
    uint32_t Bs0 = (uint32_t)__cvta_generic_to_shared(&Bs[0][0]);
    uint32_t aoff[4], boff[2];
    #pragma unroll
    for (int mi = 0; mi < 4; mi++)
        aoff[mi] = ((wm*64 + mi*16 + (msel & 1)*8 + mrow)*SW + (msel >> 1)*8)*2;
    #pragma unroll
    for (int p = 0; p < 2; p++)
        boff[p] = ((wn*32 + (p*2 + (msel >> 1))*8 + mrow)*SW + (msel & 1)*8)*2;

    float c[4][4][4];
    #pragma unroll
    for (int i = 0; i < 4; i++)
        #pragma unroll
        for (int j = 0; j < 4; j++)
            #pragma unroll
            for (int k = 0; k < 4; k++) c[i][j][k] = 0.f;

    auto loadTile = [&](int k0, int buf) {
        #pragma unroll
        for (int li = 0; li < 2; li++) {          // A: 128 rows x 32 bf16
            int idx = tid + 256*li;
            int row = idx >> 2, kc = (idx & 3) * 8;
            uint32_t s = (uint32_t)__cvta_generic_to_shared(&As[buf][row*SW + kc]);
            const __nv_bfloat16* gp = A + (size_t)(bm + row)*K + k0 + kc;
            asm volatile("cp.async.cg.shared.global [%0], [%1], 16;\n" :: "r"(s), "l"(gp));
        }
        #pragma unroll
        for (int li = 0; li < 2; li++) {          // B^T: 128 n-rows x 32 bf16
            int idx = tid + 256*li;
            int row = idx >> 2, kc = (idx & 3) * 8;
            uint32_t s = (uint32_t)__cvta_generic_to_shared(&Bs[buf][row*SW + kc]);
            const __nv_bfloat16* gp = Bt + (size_t)(bn + row)*K + k0 + kc;
            asm volatile("cp.async.cg.shared.global [%0], [%1], 16;\n" :: "r"(s), "l"(gp));
        }
        asm volatile("cp.async.commit_group;\n");
    };

    int nk = K / 32;
    loadTile(0, 0);

    for (int i = 0; i < nk; i++) {
        int cur = i & 1;
        asm volatile("cp.async.wait_group 0;\n" ::: "memory");
        __syncthreads();
        if (i + 1 < nk) loadTile((i + 1)*32, (i + 1) & 1);

        uint32_t aBuf = As0 + cur*ABUF;
        uint32_t bBuf = Bs0 + cur*ABUF;
        #pragma unroll
        for (int kk = 0; kk < 2; kk++) {          // two k16 chunks
            uint32_t kadd = kk*32;                // 16 bf16 = 32 bytes
            uint32_t a[4][4], b[4][2];
            #pragma unroll
            for (int mi = 0; mi < 4; mi++)
                LDSM4(a[mi][0], a[mi][1], a[mi][2], a[mi][3], aBuf + aoff[mi] + kadd);
            LDSM4(b[0][0], b[0][1], b[1][0], b[1][1], bBuf + boff[0] + kadd);
            LDSM4(b[2][0], b[2][1], b[3][0], b[3][1], bBuf + boff[1] + kadd);
            #pragma unroll
            for (int mi = 0; mi < 4; mi++)
                #pragma unroll
                for (int ni = 0; ni < 4; ni++)
                    asm volatile(
                        "mma.sync.aligned.m16n8k16.row.col.f32.bf16.bf16.f32 "
                        "{%0,%1,%2,%3}, {%4,%5,%6,%7}, {%8,%9}, {%0,%1,%2,%3};"
                        : "+f"(c[mi][ni][0]), "+f"(c[mi][ni][1]),
                          "+f"(c[mi][ni][2]), "+f"(c[mi][ni][3])
                        : "r"(a[mi][0]), "r"(a[mi][1]), "r"(a[mi][2]), "r"(a[mi][3]),
                          "r"(b[ni][0]), "r"(b[ni][1]));
        }
    }

    #pragma unroll
    for (int mi = 0; mi < 4; mi++) {
        #pragma unroll
        for (int ni = 0; ni < 4; ni++) {
            int row = bm + wm*64 + mi*16 + g;
            int col = bn + wn*32 + ni*8 + tg*2;
            float2 bv = *(const float2*)&bias[col];
            float v0 = c[mi][ni][0] + bv.x;
            float v1 = c[mi][ni][1] + bv.y;
            float v2 = c[mi][ni][2] + bv.x;
            float v3 = c[mi][ni][3] + bv.y;
            if (RELU) {
                v0 = fmaxf(v0, 0.f); v1 = fmaxf(v1, 0.f);
                v2 = fmaxf(v2, 0.f); v3 = fmaxf(v3, 0.f);
            }
            if (RES) {
                float2 r0 = *(const float2*)&res[(size_t)row*N + col];
                float2 r1 = *(const float2*)&res[(size_t)(row+8)*N + col];
                v0 += r0.x; v1 += r0.y; v2 += r1.x; v3 += r1.y;
            }
            if (OUTBF16) {
                __nv_bfloat16* Cb = (__nv_bfloat16*)Cm;
                *(__nv_bfloat162*)&Cb[(size_t)row*N + col] =
                    __floats2bfloat162_rn(v0, v1);
                *(__nv_bfloat162*)&Cb[(size_t)(row+8)*N + col] =
                    __floats2bfloat162_rn(v2, v3);
            } else {
                float* Cf = (float*)Cm;
                *(float2*)&Cf[(size_t)row*N + col]     = make_float2(v0, v1);
                *(float2*)&Cf[(size_t)(row+8)*N + col] = make_float2(v2, v3);
            }
        }
    }
}

// ---------------- attention scores: warp per token (bf16 h) ------------------
__global__ void __launch_bounds__(256) k_att(const float* __restrict__ att_src,
                                             const float* __restrict__ att_dst) {
    int bt   = blockIdx.x*8 + (threadIdx.x >> 5);
    int lane = threadIdx.x & 31;
    const __nv_bfloat16* hr = g_hb + (size_t)bt*CC;
    #pragma unroll
    for (int hh = 0; hh < HH; hh++) {
        float2 hv = __bfloat1622float2(*(const __nv_bfloat162*)(hr + hh*FF + lane*2));
        float2 as = *(const float2*)(att_src + hh*FF + lane*2);
        float2 ad = *(const float2*)(att_dst + hh*FF + lane*2);
        float ps = hv.x*as.x + hv.y*as.y;
        float pd = hv.x*ad.x + hv.y*ad.y;
        #pragma unroll
        for (int o = 16; o; o >>= 1) {
            ps += __shfl_xor_sync(0xffffffffu, ps, o);
            pd += __shfl_xor_sync(0xffffffffu, pd, o);
        }
        if (lane == 0) {
            g_asrc[bt*HH + hh] = ps;
            g_adst[bt*HH + hh] = pd;
        }
    }
}

// ---------------- GAT aggregate + fused LN2: ONE warp per (b,t) --------------
__global__ void __launch_bounds__(256) k_gat(const float* __restrict__ x,
                                             const float* __restrict__ b_gat,
                                             const float* __restrict__ ln2g,
                                             const float* __restrict__ ln2b,
                                             float* __restrict__ x1,
                                             __nv_bfloat16* __restrict__ h2b) {
    int w    = blockIdx.x*8 + (threadIdx.x >> 5);   // bt index
    int lane = threadIdx.x & 31;
    int t = w % TT;
    int b = w / TT;
    bool active = lane < 24;
    int grp = lane >> 3;
    int h0 = grp;
    int h1 = 3 + grp;
    int cb = lane*8;

    float adst0 = active ? g_adst[w*HH + h0] : 0.f;
    float adst1 = active ? g_adst[w*HH + h1] : 0.f;

    int beg = g_off[t], end = g_off[t+1];
    const __nv_bfloat16* hbase = g_hb + (size_t)b*TT*CC;
    const float* asrcb = g_asrc + (size_t)b*TT*HH;

    float acc0[8], acc1[8];
    #pragma unroll
    for (int k = 0; k < 8; k++) { acc0[k] = 0.f; acc1[k] = 0.f; }
    float d0 = 0.f, d1 = 0.f;

    auto edge = [&](int s) {
        if (active) {
            const __nv_bfloat16* hr = hbase + (size_t)s*CC;
            const float* arow = asrcb + s*HH;

            float a0 = arow[h0] + adst0;
            a0 = (a0 >= 0.f) ? a0 : NSLOPE*a0;
            float w0 = __expf(a0);
            uint4 hv0 = *(const uint4*)(hr + cb);
            float a1 = arow[h1] + adst1;
            a1 = (a1 >= 0.f) ? a1 : NSLOPE*a1;
            float w1 = __expf(a1);
            uint4 hv1 = *(const uint4*)(hr + 192 + cb);
            {
                float2 f0 = __bfloat1622float2(*(__nv_bfloat162*)&hv0.x);
                float2 f1 = __bfloat1622float2(*(((__nv_bfloat162*)&hv0.x)+1));
                float2 f2 = __bfloat1622float2(*(__nv_bfloat162*)&hv0.z);
                float2 f3 = __bfloat1622float2(*(((__nv_bfloat162*)&hv0.z)+1));
                acc0[0] += w0*f0.x; acc0[1] += w0*f0.y;
                acc0[2] += w0*f1.x; acc0[3] += w0*f1.y;
                acc0[4] += w0*f2.x; acc0[5] += w0*f2.y;
                acc0[6] += w0*f3.x; acc0[7] += w0*f3.y;
            }
            d0 += w0;
            {
                float2 f0 = __bfloat1622float2(*(__nv_bfloat162*)&hv1.x);
                float2 f1 = __bfloat1622float2(*(((__nv_bfloat162*)&hv1.x)+1));
                float2 f2 = __bfloat1622float2(*(__nv_bfloat162*)&hv1.z);
                float2 f3 = __bfloat1622float2(*(((__nv_bfloat162*)&hv1.z)+1));
                acc1[0] += w1*f0.x; acc1[1] += w1*f0.y;
                acc1[2] += w1*f1.x; acc1[3] += w1*f1.y;
                acc1[4] += w1*f2.x; acc1[5] += w1*f2.y;
                acc1[6] += w1*f3.x; acc1[7] += w1*f3.y;
            }
            d1 += w1;
        }
    };

    int i = beg;
    for (; i + 2 <= end; i += 2) {
        int s0 = g_csr_src[i];
        int s1 = g_csr_src[i+1];
        edge(s0);
        edge(s1);
    }
    for (; i < end; i++) edge(g_csr_src[i]);

    // x1 row values (16 per active lane) + LN2 reduction in-warp
    float vals[16];
    float sum = 0.f;
    if (active) {
        float inv0 = 1.f/d0, inv1 = 1.f/d1;
        #pragma unroll
        for (int j = 0; j < 2; j++) {
            float* acc = j ? acc1 : acc0;
            float inv = j ? inv1 : inv0;
            int col = j*192 + cb;
            size_t o = (size_t)w*CC + col;
            float4 xv0 = *(const float4*)(x + o);
            float4 xv1 = *(const float4*)(x + o + 4);
            float4 bg0 = *(const float4*)(b_gat + col);
            float4 bg1 = *(const float4*)(b_gat + col + 4);
            vals[j*8+0] = xv0.x + acc[0]*inv + bg0.x;
            vals[j*8+1] = xv0.y + acc[1]*inv + bg0.y;
            vals[j*8+2] = xv0.z + acc[2]*inv + bg0.z;
            vals[j*8+3] = xv0.w + acc[3]*inv + bg0.w;
            vals[j*8+4] = xv1.x + acc[4]*inv + bg1.x;
            vals[j*8+5] = xv1.y + acc[5]*inv + bg1.y;
            vals[j*8+6] = xv1.z + acc[6]*inv + bg1.z;
            vals[j*8+7] = xv1.w + acc[7]*inv + bg1.w;
        }
        #pragma unroll
        for (int k = 0; k < 16; k++) sum += vals[k];
    }
    #pragma unroll
    for (int o = 16; o; o >>= 1) sum += __shfl_xor_sync(0xffffffffu, sum, o);
    float mu = sum * (1.f/CC);
    float sq = 0.f;
    if (active) {
        #pragma unroll
        for (int k = 0; k < 16; k++) { float dd = vals[k]-mu; sq += dd*dd; }
    }
    #pragma unroll
    for (int o = 16; o; o >>= 1) sq += __shfl_xor_sync(0xffffffffu, sq, o);
    float rs = rsqrtf(sq*(1.f/CC) + LNEPS);

    if (active) {
        #pragma unroll
        for (int j = 0; j < 2; j++) {
            int col = j*192 + cb;
            size_t o = (size_t)w*CC + col;
            float4 r0 = make_float4(vals[j*8+0], vals[j*8+1], vals[j*8+2], vals[j*8+3]);
            float4 r1 = make_float4(vals[j*8+4], vals[j*8+5], vals[j*8+6], vals[j*8+7]);
            *(float4*)(x1 + o)     = r0;
            *(float4*)(x1 + o + 4) = r1;
            float4 g0 = *(const float4*)(ln2g + col);
            float4 g1 = *(const float4*)(ln2g + col + 4);
            float4 bb0 = *(const float4*)(ln2b + col);
            float4 bb1 = *(const float4*)(ln2b + col + 4);
            uint4 hv;
            __nv_bfloat162* hp = (__nv_bfloat162*)&hv;
            hp[0] = __floats2bfloat162_rn((r0.x-mu)*rs*g0.x + bb0.x,
                                          (r0.y-mu)*rs*g0.y + bb0.y);
            hp[1] = __floats2bfloat162_rn((r0.z-mu)*rs*g0.z + bb0.z,
                                          (r0.w-mu)*rs*g0.w + bb0.w);
            hp[2] = __floats2bfloat162_rn((r1.x-mu)*rs*g1.x + bb1.x,
                                          (r1.y-mu)*rs*g1.y + bb1.y);
            hp[3] = __floats2bfloat162_rn((r1.z-mu)*rs*g1.z + bb1.z,
                                          (r1.w-mu)*rs*g1.w + bb1.w);
            *(uint4*)(h2b + o) = hv;
        }
    }
}

// ---------------- launch ----------------------------------------------------
extern "C" void kernel_launch(void* const* d_in, const int* in_sizes, int n_in,
                              void* d_out, int out_size) {
    const float* x       = (const float*)d_in[0];
    const int*   ei      = (const int*)  d_in[1];
    const float* W_gat   = (const float*)d_in[2];
    const float* att_src = (const float*)d_in[3];
    const float* att_dst = (const float*)d_in[4];
    const float* b_gat   = (const float*)d_in[5];
    const float* ln1_g   = (const float*)d_in[6];
    const float* ln1_b   = (const float*)d_in[7];
    const float* ln2_g   = (const float*)d_in[8];
    const float* ln2_b   = (const float*)d_in[9];
    const float* W1      = (const float*)d_in[10];
    const float* b1      = (const float*)d_in[11];
    const float* W2      = (const float*)d_in[12];
    const float* b2      = (const float*)d_in[13];
    float* out = (float*)d_out;

    float* p_xn;  cudaGetSymbolAddress((void**)&p_xn,  g_xn);
    __nv_bfloat16* p_hb;  cudaGetSymbolAddress((void**)&p_hb,  g_hb);
    float* p_x1;  cudaGetSymbolAddress((void**)&p_x1,  g_x1);
    __nv_bfloat16* p_h2b; cudaGetSymbolAddress((void**)&p_h2b, g_h2b);
    __nv_bfloat16* p_ffnb;cudaGetSymbolAddress((void**)&p_ffnb,g_ffnb);
    float* p_wg;  cudaGetSymbolAddress((void**)&p_wg,  g_wg_t);
    __nv_bfloat16* p_w1t; cudaGetSymbolAddress((void**)&p_w1t, g_w1t);
    __nv_bfloat16* p_w2t; cudaGetSymbolAddress((void**)&p_w2t, g_w2t);

    // #1 weight prep (W_gat), #2 LN1, #3 zero-deg, #4 GEMM1 (ncu -s5 slot)
    k_cvt_wg<<<(CC*CC/4+255)/256, 256>>>(W_gat);
    k_ln<<<BT/8, 256>>>(x, ln1_g, ln1_b, p_xn);
    k_zero_deg<<<(TT+255)/256, 256>>>();
    k_gemm_tf32<<<dim3(CC/128, BT/128), 256>>>(p_xn, p_wg, p_hb, BT, CC, CC);

    // CSR build
    k_hist<<<(EE+255)/256, 256>>>(ei);
    k_scan<<<1, 1024>>>();
    k_fill<<<(EE+TT+255)/256, 256>>>(ei);

    // attention scores
    k_att<<<BT/8, 256>>>(att_src, att_dst);

    // gather + softmax + residual + fused LN2 -> x1 (fp32), h2 (bf16)
    k_gat<<<BT/8, 256>>>(x, b_gat, ln2_g, ln2_b, p_x1, p_h2b);

    // MLP weight transpose+convert (single launch)
    k_wt_both<<<NB1+NB2, dim3(32,8)>>>(W1, W2);

    // GEMM2 (bf16): ffn = relu(h2 @ W1 + b1) -> bf16
    k_gemm_bf<1,0,1><<<dim3(DFF/128, BT/128), 256>>>(p_h2b, p_w1t, b1, nullptr,
                                                     p_ffnb, BT, DFF, CC);
    // GEMM3 (bf16): out = ffn @ W2 + b2 + x1 -> fp32
    k_gemm_bf<0,1,0><<<dim3(CC/128, BT/128), 256>>>(p_ffnb, p_w2t, b2, p_x1,
                                                    out, BT, CC, DFF);
}

// round 12
// speedup vs baseline: 1.6380x; 1.0292x over previous
#include <cuda_runtime.h>
#include <cuda_bf16.h>
#include <stdint.h>
#include <math.h>

#define BB 8
#define TT 4096
#define CC 384
#define HH 6
#define FF 64
#define EE 131072
#define DFF 1536
#define BT (BB*TT)            // 32768
#define NSLOPE 0.2f
#define LNEPS 1e-5f

// ---------------- scratch (device globals; no allocation allowed) ------------
__device__ float g_xn [BT*CC];                // LN1 output (tf32-rounded)
__device__ __nv_bfloat16 g_hb [BT*CC];        // GAT projection h (bf16)
__device__ float g_x1 [BT*CC];                // x + gat_out (fp32, residual)
__device__ __nv_bfloat16 g_h2b[BT*CC];        // LN2 output (bf16, GEMM2 A)
__device__ __nv_bfloat16 g_ffnb[(size_t)BT*DFF]; // MLP hidden (bf16)
__device__ float g_wg_t[CC*CC];               // tf32-rounded W_gat
__device__ __nv_bfloat16 g_w1t[DFF*CC];       // W1^T bf16  [1536][384]
__device__ __nv_bfloat16 g_w2t[CC*DFF];       // W2^T bf16  [384][1536]
__device__ float g_asrc[BT*HH];
__device__ float g_adst[BT*HH];
__device__ int   g_deg [TT];
__device__ int   g_off [TT+1];
__device__ int   g_cur [TT];
__device__ int   g_csr_src[EE+TT];

__device__ __forceinline__ uint32_t f2tf32(float f) {
    uint32_t r;
    asm("cvt.rna.tf32.f32 %0, %1;" : "=r"(r) : "f"(f));
    return r;
}
__device__ __forceinline__ float f2tf32f(float f) {
    return __uint_as_float(f2tf32(f));
}

#define LDSM4(r0,r1,r2,r3,addr) \
    asm volatile("ldmatrix.sync.aligned.m8n8.x4.shared.b16 {%0,%1,%2,%3}, [%4];" \
        : "=r"(r0), "=r"(r1), "=r"(r2), "=r"(r3) : "r"(addr))

#define CP_ASYNC16(s, gp) \
    asm volatile("cp.async.cg.shared.global [%0], [%1], 16;\n" :: "r"(s), "l"(gp))
#define CP_COMMIT() asm volatile("cp.async.commit_group;\n")
#define CP_WAIT2()  asm volatile("cp.async.wait_group 2;\n" ::: "memory")

// ---------------- W_gat tf32 pre-round + deg zero (merged) -------------------
__global__ void k_cvt_wg(const float* __restrict__ wg) {
    int i = blockIdx.x*blockDim.x + threadIdx.x;
    if (i < TT) g_deg[i] = 0;
    if (i < CC*CC/4) {
        float4 v = ((const float4*)wg)[i];
        v.x = f2tf32f(v.x); v.y = f2tf32f(v.y);
        v.z = f2tf32f(v.z); v.w = f2tf32f(v.w);
        ((float4*)g_wg_t)[i] = v;
    }
}

// ---------------- weight transpose + bf16: both W1 and W2 in one launch ------
#define NB1 ((DFF/32)*(CC/32))   // 576 blocks for W1^T
#define NB2 ((CC/32)*(DFF/32))   // 576 blocks for W2^T
__global__ void k_wt_both(const float* __restrict__ W1f,
                          const float* __restrict__ W2f) {
    __shared__ __nv_bfloat16 tile[32][33];
    int bid = blockIdx.x;
    const float* W; __nv_bfloat16* WT; int K, N, bx, by;
    if (bid < NB1) { W = W1f; WT = g_w1t; K = CC;  N = DFF;
                     bx = bid % (DFF/32); by = bid / (DFF/32); }
    else           { bid -= NB1; W = W2f; WT = g_w2t; K = DFF; N = CC;
                     bx = bid % (CC/32);  by = bid / (CC/32); }
    int n0 = bx*32, k0 = by*32;
    int tx = threadIdx.x, ty = threadIdx.y;   // 32 x 8
    #pragma unroll
    for (int r = 0; r < 32; r += 8)
        tile[ty+r][tx] = __float2bfloat16(W[(size_t)(k0+ty+r)*N + n0+tx]);
    __syncthreads();
    #pragma unroll
    for (int r = 0; r < 32; r += 8)
        WT[(size_t)(n0+ty+r)*K + k0+tx] = tile[tx][ty+r];
}

// ---------------- CSR build --------------------------------------------------
__global__ void k_hist(const int* __restrict__ ei) {
    int e = blockIdx.x*blockDim.x + threadIdx.x;
    if (e < EE) atomicAdd(&g_deg[ei[EE + e]], 1);   // dst row
}

__global__ void k_scan() {   // single block, 1024 threads, 4 nodes each
    __shared__ int s[1024];
    int tid  = threadIdx.x;
    int base = tid*4;
    int v0 = g_deg[base+0] + 1;   // +1 self loop
    int v1 = g_deg[base+1] + 1;
    int v2 = g_deg[base+2] + 1;
    int v3 = g_deg[base+3] + 1;
    s[tid] = v0+v1+v2+v3;
    __syncthreads();
    for (int d = 1; d < 1024; d <<= 1) {
        int t = (tid >= d) ? s[tid-d] : 0;
        __syncthreads();
        s[tid] += t;
        __syncthreads();
    }
    int excl = (tid == 0) ? 0 : s[tid-1];
    int o0 = excl, o1 = o0+v0, o2 = o1+v1, o3 = o2+v2;
    g_off[base+0]=o0; g_off[base+1]=o1; g_off[base+2]=o2; g_off[base+3]=o3;
    g_cur[base+0]=o0; g_cur[base+1]=o1; g_cur[base+2]=o2; g_cur[base+3]=o3;
    if (tid == 1023) g_off[TT] = s[1023];
}

__global__ void k_fill(const int* __restrict__ ei) {
    int i = blockIdx.x*blockDim.x + threadIdx.x;
    if (i < EE) {
        int d = ei[EE + i];
        int p = atomicAdd(&g_cur[d], 1);
        g_csr_src[p] = ei[i];                       // src row
    } else if (i < EE + TT) {
        int t = i - EE;
        int p = atomicAdd(&g_cur[t], 1);
        g_csr_src[p] = t;                           // self loop
    }
}

// ---------------- layer norm 1: warp per row, 12 elems/lane ------------------
__global__ void __launch_bounds__(256) k_ln(const float* __restrict__ x,
                                            const float* __restrict__ g,
                                            const float* __restrict__ b,
                                            float* __restrict__ out) {
    int row  = blockIdx.x*8 + (threadIdx.x >> 5);
    int lane = threadIdx.x & 31;
    const float* xr = x + (size_t)row*CC;
    float v[12];
    float sum = 0.f;
    #pragma unroll
    for (int i = 0; i < 12; i++) { v[i] = xr[lane + i*32]; sum += v[i]; }
    #pragma unroll
    for (int o = 16; o; o >>= 1) sum += __shfl_xor_sync(0xffffffffu, sum, o);
    float mu  = sum * (1.f/CC);
    float var = 0.f;
    #pragma unroll
    for (int i = 0; i < 12; i++) { float d = v[i]-mu; var += d*d; }
    #pragma unroll
    for (int o = 16; o; o >>= 1) var += __shfl_xor_sync(0xffffffffu, var, o);
    float rs = rsqrtf(var*(1.f/CC) + LNEPS);
    float* orow = out + (size_t)row*CC;
    #pragma unroll
    for (int i = 0; i < 12; i++) {
        int c = lane + i*32;
        orow[c] = f2tf32f((v[i]-mu)*rs*g[c] + b[c]);
    }
}

// ---------------- tf32 tensor-core GEMM (GEMM1), 4-stage cp.async ------------
#define SA 20
#define SB 136
#define TFA (128*SA)                // floats per A stage
#define TFB (16*SB)                 // floats per B stage
#define TF32_SMEM (4*(TFA+TFB)*4)   // 75776 B

__global__ void __launch_bounds__(256) k_gemm_tf32(const float* __restrict__ A,
                                                   const float* __restrict__ Bm,
                                                   __nv_bfloat16* __restrict__ Cm,
                                                   int M, int N, int K) {
    extern __shared__ float dsf[];
    float* AsB = dsf;           // 4 stages x TFA
    float* BsB = dsf + 4*TFA;   // 4 stages x TFB

    int tid  = threadIdx.x;
    int lane = tid & 31;
    int w    = tid >> 5;
    int g    = lane >> 2;
    int tg   = lane & 3;
    int wm   = w & 1;
    int wn   = w >> 1;
    int bm   = blockIdx.y * 128;
    int bn   = blockIdx.x * 128;

    float c[4][4][4];
    #pragma unroll
    for (int i = 0; i < 4; i++)
        #pragma unroll
        for (int j = 0; j < 4; j++)
            #pragma unroll
            for (int k = 0; k < 4; k++) c[i][j][k] = 0.f;

    auto loadTile = [&](int k0, int buf) {
        float* Ab = AsB + buf*TFA;
        float* Bb = BsB + buf*TFB;
        #pragma unroll
        for (int li = 0; li < 2; li++) {
            int idx = tid + 256*li;
            int row = idx >> 2, kc = (idx & 3) * 4;
            uint32_t s = (uint32_t)__cvta_generic_to_shared(&Ab[row*SA + kc]);
            CP_ASYNC16(s, A + (size_t)(bm + row)*K + k0 + kc);
        }
        #pragma unroll
        for (int li = 0; li < 2; li++) {
            int idx = tid + 256*li;
            int kr = idx >> 5, nc = (idx & 31) * 4;
            uint32_t s = (uint32_t)__cvta_generic_to_shared(&Bb[kr*SB + nc]);
            CP_ASYNC16(s, Bm + (size_t)(k0 + kr)*N + bn + nc);
        }
        CP_COMMIT();
    };

    int nk = K / 16;                       // 24
    loadTile(0, 0); loadTile(16, 1); loadTile(32, 2);

    for (int i = 0; i < nk; i++) {
        CP_WAIT2();
        __syncthreads();
        if (i + 3 < nk) loadTile((i + 3)*16, (i + 3) & 3);
        else            CP_COMMIT();       // keep group count invariant (tail!)

        const float* Ab = AsB + (i & 3)*TFA;
        const float* Bb = BsB + (i & 3)*TFB;
        #pragma unroll
        for (int ks = 0; ks < 2; ks++) {
            uint32_t a[4][4], b[4][2];
            #pragma unroll
            for (int mi = 0; mi < 4; mi++) {
                int r0 = wm*64 + mi*16 + g;
                a[mi][0] = __float_as_uint(Ab[ r0    *SA + ks*8 + tg    ]);
                a[mi][1] = __float_as_uint(Ab[(r0+8) *SA + ks*8 + tg    ]);
                a[mi][2] = __float_as_uint(Ab[ r0    *SA + ks*8 + tg + 4]);
                a[mi][3] = __float_as_uint(Ab[(r0+8) *SA + ks*8 + tg + 4]);
            }
            #pragma unroll
            for (int ni = 0; ni < 4; ni++) {
                int cc = wn*32 + ni*8 + g;
                b[ni][0] = __float_as_uint(Bb[(ks*8 + tg    )*SB + cc]);
                b[ni][1] = __float_as_uint(Bb[(ks*8 + tg + 4)*SB + cc]);
            }
            #pragma unroll
            for (int mi = 0; mi < 4; mi++)
                #pragma unroll
                for (int ni = 0; ni < 4; ni++)
                    asm volatile(
                        "mma.sync.aligned.m16n8k8.row.col.f32.tf32.tf32.f32 "
                        "{%0,%1,%2,%3}, {%4,%5,%6,%7}, {%8,%9}, {%0,%1,%2,%3};"
                        : "+f"(c[mi][ni][0]), "+f"(c[mi][ni][1]),
                          "+f"(c[mi][ni][2]), "+f"(c[mi][ni][3])
                        : "r"(a[mi][0]), "r"(a[mi][1]), "r"(a[mi][2]), "r"(a[mi][3]),
                          "r"(b[ni][0]), "r"(b[ni][1]));
        }
    }

    #pragma unroll
    for (int mi = 0; mi < 4; mi++) {
        #pragma unroll
        for (int ni = 0; ni < 4; ni++) {
            int row = bm + wm*64 + mi*16 + g;
            int col = bn + wn*32 + ni*8 + tg*2;
            *(__nv_bfloat162*)&Cm[(size_t)row*N + col] =
                __floats2bfloat162_rn(c[mi][ni][0], c[mi][ni][1]);
            *(__nv_bfloat162*)&Cm[(size_t)(row+8)*N + col] =
                __floats2bfloat162_rn(c[mi][ni][2], c[mi][ni][3]);
        }
    }
}

// ---------------- bf16 tensor-core GEMM (MLP), 4-stage + ldmatrix ------------
#define SW 40                       // bf16 row stride; 80B rows, LDSM-safe
#define ABUF (128*SW*2)             // 10240 B per A (or B) stage
#define BF16_SMEM (8*ABUF)          // 81920 B (4 stages x (A+B))

template<int RELU, int RES, int OUTBF16>
__global__ void __launch_bounds__(256) k_gemm_bf(const __nv_bfloat16* __restrict__ A,
                                                 const __nv_bfloat16* __restrict__ Bt,
                                                 const float* __restrict__ bias,
                                                 const float* __restrict__ res,
                                                 void* __restrict__ Cm,
                                                 int M, int N, int K) {
    extern __shared__ __nv_bfloat16 dsb[];
    __nv_bfloat16* AsB = dsb;               // 4 stages x 128*SW
    __nv_bfloat16* BsB = dsb + 4*128*SW;    // 4 stages x 128*SW

    int tid  = threadIdx.x;
    int lane = tid & 31;
    int w    = tid >> 5;
    int g    = lane >> 2;
    int tg   = lane & 3;
    int wm   = w & 1;
    int wn   = w >> 1;
    int bm   = blockIdx.y * 128;
    int bn   = blockIdx.x * 128;

    int mrow = lane & 7;
    int msel = lane >> 3;
    uint32_t As0 = (uint32_t)__cvta_generic_to_shared(AsB);
    uint32_t Bs0 = (uint32_t)__cvta_generic_to_shared(BsB);
    uint32_t aoff[4], boff[2];
    #pragma unroll
    for (int mi = 0; mi < 4; mi++)
        aoff[mi] = ((wm*64 + mi*16 + (msel & 1)*8 + mrow)*SW + (msel >> 1)*8)*2;
    #pragma unroll
    for (int p = 0; p < 2; p++)
        boff[p] = ((wn*32 + (p*2 + (msel >> 1))*8 + mrow)*SW + (msel & 1)*8)*2;

    float c[4][4][4];
    #pragma unroll
    for (int i = 0; i < 4; i++)
        #pragma unroll
        for (int j = 0; j < 4; j++)
            #pragma unroll
            for (int k = 0; k < 4; k++) c[i][j][k] = 0.f;

    auto loadTile = [&](int k0, int buf) {
        __nv_bfloat16* Ab = AsB + buf*128*SW;
        __nv_bfloat16* Bb = BsB + buf*128*SW;
        #pragma unroll
        for (int li = 0; li < 2; li++) {
            int idx = tid + 256*li;
            int row = idx >> 2, kc = (idx & 3) * 8;
            uint32_t s = (uint32_t)__cvta_generic_to_shared(&Ab[row*SW + kc]);
            CP_ASYNC16(s, A + (size_t)(bm + row)*K + k0 + kc);
        }
        #pragma unroll
        for (int li = 0; li < 2; li++) {
            int idx = tid + 256*li;
            int row = idx >> 2, kc = (idx & 3) * 8;
            uint32_t s = (uint32_t)__cvta_generic_to_shared(&Bb[row*SW + kc]);
            CP_ASYNC16(s, Bt + (size_t)(bn + row)*K + k0 + kc);
        }
        CP_COMMIT();
    };

    int nk = K / 32;                        // 12 or 48
    loadTile(0, 0); loadTile(32, 1); loadTile(64, 2);

    for (int i = 0; i < nk; i++) {
        CP_WAIT2();
        __syncthreads();
        if (i + 3 < nk) loadTile((i + 3)*32, (i + 3) & 3);
        else            CP_COMMIT();        // tail group-count invariant

        uint32_t aBuf = As0 + (i & 3)*ABUF;
        uint32_t bBuf = Bs0 + (i & 3)*ABUF;
        #pragma unroll
        for (int kk = 0; kk < 2; kk++) {
            uint32_t kadd = kk*32;
            uint32_t a[4][4], b[4][2];
            #pragma unroll
            for (int mi = 0; mi < 4; mi++)
                LDSM4(a[mi][0], a[mi][1], a[mi][2], a[mi][3], aBuf + aoff[mi] + kadd);
            LDSM4(b[0][0], b[0][1], b[1][0], b[1][1], bBuf + boff[0] + kadd);
            LDSM4(b[2][0], b[2][1], b[3][0], b[3][1], bBuf + boff[1] + kadd);
            #pragma unroll
            for (int mi = 0; mi < 4; mi++)
                #pragma unroll
                for (int ni = 0; ni < 4; ni++)
                    asm volatile(
                        "mma.sync.aligned.m16n8k16.row.col.f32.bf16.bf16.f32 "
                        "{%0,%1,%2,%3}, {%4,%5,%6,%7}, {%8,%9}, {%0,%1,%2,%3};"
                        : "+f"(c[mi][ni][0]), "+f"(c[mi][ni][1]),
                          "+f"(c[mi][ni][2]), "+f"(c[mi][ni][3])
                        : "r"(a[mi][0]), "r"(a[mi][1]), "r"(a[mi][2]), "r"(a[mi][3]),
                          "r"(b[ni][0]), "r"(b[ni][1]));
        }
    }

    #pragma unroll
    for (int mi = 0; mi < 4; mi++) {
        #pragma unroll
        for (int ni = 0; ni < 4; ni++) {
            int row = bm + wm*64 + mi*16 + g;
            int col = bn + wn*32 + ni*8 + tg*2;
            float2 bv = *(const float2*)&bias[col];
            float v0 = c[mi][ni][0] + bv.x;
            float v1 = c[mi][ni][1] + bv.y;
            float v2 = c[mi][ni][2] + bv.x;
            float v3 = c[mi][ni][3] + bv.y;
            if (RELU) {
                v0 = fmaxf(v0, 0.f); v1 = fmaxf(v1, 0.f);
                v2 = fmaxf(v2, 0.f); v3 = fmaxf(v3, 0.f);
            }
            if (RES) {
                float2 r0 = *(const float2*)&res[(size_t)row*N + col];
                float2 r1 = *(const float2*)&res[(size_t)(row+8)*N + col];
                v0 += r0.x; v1 += r0.y; v2 += r1.x; v3 += r1.y;
            }
            if (OUTBF16) {
                __nv_bfloat16* Cb = (__nv_bfloat16*)Cm;
                *(__nv_bfloat162*)&Cb[(size_t)row*N + col] =
                    __floats2bfloat162_rn(v0, v1);
                *(__nv_bfloat162*)&Cb[(size_t)(row+8)*N + col] =
                    __floats2bfloat162_rn(v2, v3);
            } else {
                float* Cf = (float*)Cm;
                *(float2*)&Cf[(size_t)row*N + col]     = make_float2(v0, v1);
                *(float2*)&Cf[(size_t)(row+8)*N + col] = make_float2(v2, v3);
            }
        }
    }
}

// ---------------- attention scores: warp per token (bf16 h) ------------------
__global__ void __launch_bounds__(256) k_att(const float* __restrict__ att_src,
                                             const float* __restrict__ att_dst) {
    int bt   = blockIdx.x*8 + (threadIdx.x >> 5);
    int lane = threadIdx.x & 31;
    const __nv_bfloat16* hr = g_hb + (size_t)bt*CC;
    #pragma unroll
    for (int hh = 0; hh < HH; hh++) {
        float2 hv = __bfloat1622float2(*(const __nv_bfloat162*)(hr + hh*FF + lane*2));
        float2 as = *(const float2*)(att_src + hh*FF + lane*2);
        float2 ad = *(const float2*)(att_dst + hh*FF + lane*2);
        float ps = hv.x*as.x + hv.y*as.y;
        float pd = hv.x*ad.x + hv.y*ad.y;
        #pragma unroll
        for (int o = 16; o; o >>= 1) {
            ps += __shfl_xor_sync(0xffffffffu, ps, o);
            pd += __shfl_xor_sync(0xffffffffu, pd, o);
        }
        if (lane == 0) {
            g_asrc[bt*HH + hh] = ps;
            g_adst[bt*HH + hh] = pd;
        }
    }
}

// ---------------- GAT aggregate + fused LN2: ONE warp per (b,t) --------------
__global__ void __launch_bounds__(256) k_gat(const float* __restrict__ x,
                                             const float* __restrict__ b_gat,
                                             const float* __restrict__ ln2g,
                                             const float* __restrict__ ln2b,
                                             float* __restrict__ x1,
                                             __nv_bfloat16* __restrict__ h2b) {
    int w    = blockIdx.x*8 + (threadIdx.x >> 5);   // bt index
    int lane = threadIdx.x & 31;
    int t = w % TT;
    int b = w / TT;
    bool active = lane < 24;
    int grp = lane >> 3;
    int h0 = grp;
    int h1 = 3 + grp;
    int cb = lane*8;

    float adst0 = active ? g_adst[w*HH + h0] : 0.f;
    float adst1 = active ? g_adst[w*HH + h1] : 0.f;

    int beg = g_off[t], end = g_off[t+1];
    const __nv_bfloat16* hbase = g_hb + (size_t)b*TT*CC;
    const float* asrcb = g_asrc + (size_t)b*TT*HH;

    float acc0[8], acc1[8];
    #pragma unroll
    for (int k = 0; k < 8; k++) { acc0[k] = 0.f; acc1[k] = 0.f; }
    float d0 = 0.f, d1 = 0.f;

    auto edge = [&](int s) {
        if (active) {
            const __nv_bfloat16* hr = hbase + (size_t)s*CC;
            const float* arow = asrcb + s*HH;

            float a0 = arow[h0] + adst0;
            a0 = (a0 >= 0.f) ? a0 : NSLOPE*a0;
            float w0 = __expf(a0);
            uint4 hv0 = *(const uint4*)(hr + cb);
            float a1 = arow[h1] + adst1;
            a1 = (a1 >= 0.f) ? a1 : NSLOPE*a1;
            float w1 = __expf(a1);
            uint4 hv1 = *(const uint4*)(hr + 192 + cb);
            {
                float2 f0 = __bfloat1622float2(*(__nv_bfloat162*)&hv0.x);
                float2 f1 = __bfloat1622float2(*(((__nv_bfloat162*)&hv0.x)+1));
                float2 f2 = __bfloat1622float2(*(__nv_bfloat162*)&hv0.z);
                float2 f3 = __bfloat1622float2(*(((__nv_bfloat162*)&hv0.z)+1));
                acc0[0] += w0*f0.x; acc0[1] += w0*f0.y;
                acc0[2] += w0*f1.x; acc0[3] += w0*f1.y;
                acc0[4] += w0*f2.x; acc0[5] += w0*f2.y;
                acc0[6] += w0*f3.x; acc0[7] += w0*f3.y;
            }
            d0 += w0;
            {
                float2 f0 = __bfloat1622float2(*(__nv_bfloat162*)&hv1.x);
                float2 f1 = __bfloat1622float2(*(((__nv_bfloat162*)&hv1.x)+1));
                float2 f2 = __bfloat1622float2(*(__nv_bfloat162*)&hv1.z);
                float2 f3 = __bfloat1622float2(*(((__nv_bfloat162*)&hv1.z)+1));
                acc1[0] += w1*f0.x; acc1[1] += w1*f0.y;
                acc1[2] += w1*f1.x; acc1[3] += w1*f1.y;
                acc1[4] += w1*f2.x; acc1[5] += w1*f2.y;
                acc1[6] += w1*f3.x; acc1[7] += w1*f3.y;
            }
            d1 += w1;
        }
    };

    int i = beg;
    for (; i + 2 <= end; i += 2) {
        int s0 = g_csr_src[i];
        int s1 = g_csr_src[i+1];
        edge(s0);
        edge(s1);
    }
    for (; i < end; i++) edge(g_csr_src[i]);

    float vals[16];
    float sum = 0.f;
    if (active) {
        float inv0 = 1.f/d0, inv1 = 1.f/d1;
        #pragma unroll
        for (int j = 0; j < 2; j++) {
            float* acc = j ? acc1 : acc0;
            float inv = j ? inv1 : inv0;
            int col = j*192 + cb;
            size_t o = (size_t)w*CC + col;
            float4 xv0 = *(const float4*)(x + o);
            float4 xv1 = *(const float4*)(x + o + 4);
            float4 bg0 = *(const float4*)(b_gat + col);
            float4 bg1 = *(const float4*)(b_gat + col + 4);
            vals[j*8+0] = xv0.x + acc[0]*inv + bg0.x;
            vals[j*8+1] = xv0.y + acc[1]*inv + bg0.y;
            vals[j*8+2] = xv0.z + acc[2]*inv + bg0.z;
            vals[j*8+3] = xv0.w + acc[3]*inv + bg0.w;
            vals[j*8+4] = xv1.x + acc[4]*inv + bg1.x;
            vals[j*8+5] = xv1.y + acc[5]*inv + bg1.y;
            vals[j*8+6] = xv1.z + acc[6]*inv + bg1.z;
            vals[j*8+7] = xv1.w + acc[7]*inv + bg1.w;
        }
        #pragma unroll
        for (int k = 0; k < 16; k++) sum += vals[k];
    }
    #pragma unroll
    for (int o = 16; o; o >>= 1) sum += __shfl_xor_sync(0xffffffffu, sum, o);
    float mu = sum * (1.f/CC);
    float sq = 0.f;
    if (active) {
        #pragma unroll
        for (int k = 0; k < 16; k++) { float dd = vals[k]-mu; sq += dd*dd; }
    }
    #pragma unroll
    for (int o = 16; o; o >>= 1) sq += __shfl_xor_sync(0xffffffffu, sq, o);
    float rs = rsqrtf(sq*(1.f/CC) + LNEPS);

    if (active) {
        #pragma unroll
        for (int j = 0; j < 2; j++) {
            int col = j*192 + cb;
            size_t o = (size_t)w*CC + col;
            float4 r0 = make_float4(vals[j*8+0], vals[j*8+1], vals[j*8+2], vals[j*8+3]);
            float4 r1 = make_float4(vals[j*8+4], vals[j*8+5], vals[j*8+6], vals[j*8+7]);
            *(float4*)(x1 + o)     = r0;
            *(float4*)(x1 + o + 4) = r1;
            float4 g0 = *(const float4*)(ln2g + col);
            float4 g1 = *(const float4*)(ln2g + col + 4);
            float4 bb0 = *(const float4*)(ln2b + col);
            float4 bb1 = *(const float4*)(ln2b + col + 4);
            uint4 hv;
            __nv_bfloat162* hp = (__nv_bfloat162*)&hv;
            hp[0] = __floats2bfloat162_rn((r0.x-mu)*rs*g0.x + bb0.x,
                                          (r0.y-mu)*rs*g0.y + bb0.y);
            hp[1] = __floats2bfloat162_rn((r0.z-mu)*rs*g0.z + bb0.z,
                                          (r0.w-mu)*rs*g0.w + bb0.w);
            hp[2] = __floats2bfloat162_rn((r1.x-mu)*rs*g1.x + bb1.x,
                                          (r1.y-mu)*rs*g1.y + bb1.y);
            hp[3] = __floats2bfloat162_rn((r1.z-mu)*rs*g1.z + bb1.z,
                                          (r1.w-mu)*rs*g1.w + bb1.w);
            *(uint4*)(h2b + o) = hv;
        }
    }
}

// ---------------- launch ----------------------------------------------------
extern "C" void kernel_launch(void* const* d_in, const int* in_sizes, int n_in,
                              void* d_out, int out_size) {
    const float* x       = (const float*)d_in[0];
    const int*   ei      = (const int*)  d_in[1];
    const float* W_gat   = (const float*)d_in[2];
    const float* att_src = (const float*)d_in[3];
    const float* att_dst = (const float*)d_in[4];
    const float* b_gat   = (const float*)d_in[5];
    const float* ln1_g   = (const float*)d_in[6];
    const float* ln1_b   = (const float*)d_in[7];
    const float* ln2_g   = (const float*)d_in[8];
    const float* ln2_b   = (const float*)d_in[9];
    const float* W1      = (const float*)d_in[10];
    const float* b1      = (const float*)d_in[11];
    const float* W2      = (const float*)d_in[12];
    const float* b2      = (const float*)d_in[13];
    float* out = (float*)d_out;

    float* p_xn;  cudaGetSymbolAddress((void**)&p_xn,  g_xn);
    __nv_bfloat16* p_hb;  cudaGetSymbolAddress((void**)&p_hb,  g_hb);
    float* p_x1;  cudaGetSymbolAddress((void**)&p_x1,  g_x1);
    __nv_bfloat16* p_h2b; cudaGetSymbolAddress((void**)&p_h2b, g_h2b);
    __nv_bfloat16* p_ffnb;cudaGetSymbolAddress((void**)&p_ffnb,g_ffnb);
    float* p_wg;  cudaGetSymbolAddress((void**)&p_wg,  g_wg_t);
    __nv_bfloat16* p_w1t; cudaGetSymbolAddress((void**)&p_w1t, g_w1t);
    __nv_bfloat16* p_w2t; cudaGetSymbolAddress((void**)&p_w2t, g_w2t);

    // opt-in dynamic smem (idempotent, host-side; capture-safe)
    cudaFuncSetAttribute(k_gemm_tf32,
        cudaFuncAttributeMaxDynamicSharedMemorySize, TF32_SMEM);
    cudaFuncSetAttribute(k_gemm_bf<1,0,1>,
        cudaFuncAttributeMaxDynamicSharedMemorySize, BF16_SMEM);
    cudaFuncSetAttribute(k_gemm_bf<0,1,0>,
        cudaFuncAttributeMaxDynamicSharedMemorySize, BF16_SMEM);

    // #1 cvt+zero, #2 LN1, #3 hist, #4 GEMM1 (profiled slot)
    k_cvt_wg<<<(CC*CC/4+255)/256, 256>>>(W_gat);
    k_ln<<<BT/8, 256>>>(x, ln1_g, ln1_b, p_xn);
    k_hist<<<(EE+255)/256, 256>>>(ei);
    k_gemm_tf32<<<dim3(CC/128, BT/128), 256, TF32_SMEM>>>(p_xn, p_wg, p_hb,
                                                          BT, CC, CC);
    k_scan<<<1, 1024>>>();
    k_fill<<<(EE+TT+255)/256, 256>>>(ei);

    k_att<<<BT/8, 256>>>(att_src, att_dst);
    k_gat<<<BT/8, 256>>>(x, b_gat, ln2_g, ln2_b, p_x1, p_h2b);

    k_wt_both<<<NB1+NB2, dim3(32,8)>>>(W1, W2);

    k_gemm_bf<1,0,1><<<dim3(DFF/128, BT/128), 256, BF16_SMEM>>>(
        p_h2b, p_w1t, b1, nullptr, p_ffnb, BT, DFF, CC);
    k_gemm_bf<0,1,0><<<dim3(CC/128, BT/128), 256, BF16_SMEM>>>(
        p_ffnb, p_w2t, b2, p_x1, out, BT, CC, DFF);
}